// round 2
// baseline (speedup 1.0000x reference)
#include <cuda_runtime.h>
#include <math.h>
#include <stdint.h>

#define D_MODEL 1024
#define N_STATE 16
#define E_INNER 2048
#define K_CONV  4
#define DT_RANK 64
#define BATCH   4
#define SEQ     1024
#define NTOK    (BATCH*SEQ)           // 4096
#define XDB_W   (DT_RANK + 2*N_STATE) // 160

// ---------------- scratch (device globals: allocation-free) ----------------
__device__ float g_xnorm[(size_t)NTOK * D_MODEL];        // 16 MB
__device__ float g_xz   [(size_t)NTOK * 2 * E_INNER];    // 64 MB
__device__ float g_xact [(size_t)NTOK * E_INNER];        // 32 MB
__device__ float g_xdb  [(size_t)NTOK * XDB_W];          // 2.6 MB
__device__ float g_delta[(size_t)NTOK * E_INNER];        // 32 MB
__device__ float g_y    [(size_t)NTOK * E_INNER];        // 32 MB

// ---------------- RMSNorm ----------------
__global__ void rmsnorm_kernel(const float* __restrict__ x,
                               const float* __restrict__ w,
                               float* __restrict__ out) {
    int t   = blockIdx.x;          // token
    int tid = threadIdx.x;         // 256 threads, 4 floats each
    const float4* xr = reinterpret_cast<const float4*>(x) + (size_t)t * (D_MODEL / 4);
    float4 xv = xr[tid];
    float s = xv.x*xv.x + xv.y*xv.y + xv.z*xv.z + xv.w*xv.w;
    #pragma unroll
    for (int o = 16; o > 0; o >>= 1) s += __shfl_xor_sync(0xffffffffu, s, o);
    __shared__ float red[8];
    if ((tid & 31) == 0) red[tid >> 5] = s;
    __syncthreads();
    if (tid == 0) {
        float tot = 0.f;
        #pragma unroll
        for (int i = 0; i < 8; i++) tot += red[i];
        red[0] = tot;
    }
    __syncthreads();
    float r = rsqrtf(red[0] * (1.0f / D_MODEL) + 1e-6f);
    float4 wv = reinterpret_cast<const float4*>(w)[tid];
    float4 o4 = make_float4(xv.x * r * wv.x, xv.y * r * wv.y,
                            xv.z * r * wv.z, xv.w * r * wv.w);
    reinterpret_cast<float4*>(out)[(size_t)t * (D_MODEL / 4) + tid] = o4;
}

// ---------------- generic tiled fp32 GEMM ----------------
// C[M,N] = A[M,K] @ B[K,N]; row-major with leading dims.
// EPI: 0 = plain, 1 = softplus(acc + bias[col]), 2 = acc + add[r,col]
template<int BM, int BN, int BK, int TM, int TN, int EPI>
__global__ __launch_bounds__((BM/TM)*(BN/TN))
void gemm_kernel(const float* __restrict__ A, int lda,
                 const float* __restrict__ B, int ldb,
                 float* __restrict__ C, int ldc,
                 int M, int N, int K,
                 const float* __restrict__ bias,
                 const float* __restrict__ add, int ldadd) {
    constexpr int TX = BN / TN;
    constexpr int TY = BM / TM;
    constexpr int NT = TX * TY;
    static_assert(BM * BK == NT * 4, "A tile load mapping");
    static_assert(BK * BN == NT * 4, "B tile load mapping");

    __shared__ float As[BK][BM];
    __shared__ float Bs[BK][BN];

    int tid = threadIdx.x;
    int tx = tid % TX, ty = tid / TX;
    int row0 = blockIdx.y * BM;
    int col0 = blockIdx.x * BN;

    constexpr int AKV = BK / 4;   // float4 per A row
    int arow  = tid / AKV;
    int acol4 = (tid % AKV) * 4;
    constexpr int BNV = BN / 4;   // float4 per B row
    int bkrow = tid / BNV;
    int bcol4 = (tid % BNV) * 4;

    float acc[TM][TN];
    #pragma unroll
    for (int i = 0; i < TM; i++)
        #pragma unroll
        for (int j = 0; j < TN; j++) acc[i][j] = 0.f;

    for (int k0 = 0; k0 < K; k0 += BK) {
        float4 av = *reinterpret_cast<const float4*>(
            A + (size_t)(row0 + arow) * lda + k0 + acol4);
        As[acol4 + 0][arow] = av.x;
        As[acol4 + 1][arow] = av.y;
        As[acol4 + 2][arow] = av.z;
        As[acol4 + 3][arow] = av.w;

        int gcol = col0 + bcol4;
        float4 bv = make_float4(0.f, 0.f, 0.f, 0.f);
        if (gcol < N)
            bv = *reinterpret_cast<const float4*>(
                B + (size_t)(k0 + bkrow) * ldb + gcol);
        *reinterpret_cast<float4*>(&Bs[bkrow][bcol4]) = bv;

        __syncthreads();

        #pragma unroll
        for (int kk = 0; kk < BK; kk++) {
            float a[TM], b[TN];
            #pragma unroll
            for (int i4 = 0; i4 < TM / 4; i4++) {
                float4 t = *reinterpret_cast<const float4*>(&As[kk][ty * TM + i4 * 4]);
                a[i4*4+0] = t.x; a[i4*4+1] = t.y; a[i4*4+2] = t.z; a[i4*4+3] = t.w;
            }
            #pragma unroll
            for (int j4 = 0; j4 < TN / 4; j4++) {
                float4 t = *reinterpret_cast<const float4*>(&Bs[kk][tx * TN + j4 * 4]);
                b[j4*4+0] = t.x; b[j4*4+1] = t.y; b[j4*4+2] = t.z; b[j4*4+3] = t.w;
            }
            #pragma unroll
            for (int i = 0; i < TM; i++)
                #pragma unroll
                for (int j = 0; j < TN; j++)
                    acc[i][j] = fmaf(a[i], b[j], acc[i][j]);
        }
        __syncthreads();
    }

    #pragma unroll
    for (int i = 0; i < TM; i++) {
        int r = row0 + ty * TM + i;
        #pragma unroll
        for (int j = 0; j < TN; j++) {
            int cc = col0 + tx * TN + j;
            if (cc < N) {
                float v = acc[i][j];
                if constexpr (EPI == 1) {
                    v += bias[cc];
                    v = (v > 20.f) ? v : log1pf(__expf(v));
                } else if constexpr (EPI == 2) {
                    v += add[(size_t)r * ldadd + cc];
                }
                C[(size_t)r * ldc + cc] = v;
            }
        }
    }
}

// ---------------- causal depthwise conv (K=4) + SiLU ----------------
// reads x_in = xz[:, 0:E_INNER]; writes x_act [NTOK, E_INNER]
__global__ void conv_silu_kernel(const float* __restrict__ xz,
                                 const float* __restrict__ conv_w,
                                 float* __restrict__ xact) {
    int e  = blockIdx.x * blockDim.x + threadIdx.x;   // 0..2047
    int l0 = blockIdx.y * 64;                         // L chunk
    int b  = blockIdx.z;
    float w0 = conv_w[e * 4 + 0];
    float w1 = conv_w[e * 4 + 1];
    float w2 = conv_w[e * 4 + 2];
    float w3 = conv_w[e * 4 + 3];
    float x0 = 0.f, x1 = 0.f, x2 = 0.f;
    #pragma unroll
    for (int j = -3; j < 0; j++) {
        int l = l0 + j;
        float v = (l >= 0) ? xz[((size_t)(b * SEQ + l)) * (2 * E_INNER) + e] : 0.f;
        x0 = x1; x1 = x2; x2 = v;
    }
    for (int i = 0; i < 64; i++) {
        int l = l0 + i;
        float x3 = xz[((size_t)(b * SEQ + l)) * (2 * E_INNER) + e];
        float s = w0 * x0 + w1 * x1 + w2 * x2 + w3 * x3;
        s = s / (1.f + __expf(-s));   // SiLU
        xact[((size_t)(b * SEQ + l)) * E_INNER + e] = s;
        x0 = x1; x1 = x2; x2 = x3;
    }
}

// ---------------- selective scan + gate (y *= silu(z)) + h_last ----------------
// 16 lanes per (b,e) channel, lane n owns state n.
__global__ void scan_kernel(const float* __restrict__ xz,
                            const float* __restrict__ xact,
                            const float* __restrict__ delta,
                            const float* __restrict__ xdb,
                            const float* __restrict__ A_log,
                            const float* __restrict__ D_param,
                            float* __restrict__ y,
                            float* __restrict__ hlast) {
    int gid = blockIdx.x * blockDim.x + threadIdx.x;
    int c = gid >> 4;        // channel = b*E_INNER + e
    int n = gid & 15;        // state index
    int b = c >> 11;         // / 2048
    int e = c & (E_INNER - 1);

    float An = -__expf(A_log[e * N_STATE + n]);
    float Dp = D_param[e];
    float h = 0.f;

    size_t tok = (size_t)b * SEQ;
    for (int l = 0; l < SEQ; l++) {
        size_t row = tok + l;
        float dlt = delta[row * E_INNER + e];
        float u   = xact [row * E_INNER + e];
        float Bv  = xdb[row * XDB_W + DT_RANK + n];
        float Cv  = xdb[row * XDB_W + DT_RANK + N_STATE + n];
        float dA  = __expf(dlt * An);
        h = fmaf(dA, h, dlt * u * Bv);
        float p = h * Cv;
        p += __shfl_xor_sync(0xffffffffu, p, 1, 16);
        p += __shfl_xor_sync(0xffffffffu, p, 2, 16);
        p += __shfl_xor_sync(0xffffffffu, p, 4, 16);
        p += __shfl_xor_sync(0xffffffffu, p, 8, 16);
        if (n == 0) {
            float zv = xz[row * (2 * E_INNER) + E_INNER + e];
            float yv = (p + u * Dp) * (zv / (1.f + __expf(-zv)));
            y[row * E_INNER + e] = yv;
        }
    }
    hlast[(size_t)c * N_STATE + n] = h;
}

// ---------------- launch ----------------
extern "C" void kernel_launch(void* const* d_in, const int* in_sizes, int n_in,
                              void* d_out, int out_size) {
    const float* hidden  = (const float*)d_in[0];
    const float* norm_w  = (const float*)d_in[1];
    const float* W_in    = (const float*)d_in[2];
    const float* conv_w  = (const float*)d_in[3];
    const float* W_x     = (const float*)d_in[4];
    const float* W_dt    = (const float*)d_in[5];
    const float* b_dt    = (const float*)d_in[6];
    const float* A_log   = (const float*)d_in[7];
    const float* D_param = (const float*)d_in[8];
    const float* W_out   = (const float*)d_in[9];

    float* out   = (float*)d_out;
    float* hlast = out + (size_t)NTOK * D_MODEL;

    float *xnorm, *xz, *xact, *xdb, *delta, *y;
    cudaGetSymbolAddress((void**)&xnorm, g_xnorm);
    cudaGetSymbolAddress((void**)&xz,    g_xz);
    cudaGetSymbolAddress((void**)&xact,  g_xact);
    cudaGetSymbolAddress((void**)&xdb,   g_xdb);
    cudaGetSymbolAddress((void**)&delta, g_delta);
    cudaGetSymbolAddress((void**)&y,     g_y);

    // 1. RMSNorm
    rmsnorm_kernel<<<NTOK, 256>>>(hidden, norm_w, xnorm);

    // 2. GEMM1: xz = xnorm @ W_in   [4096,1024]x[1024,4096]
    {
        dim3 g(2 * E_INNER / 128, NTOK / 128);
        gemm_kernel<128,128,8,8,8,0><<<g, 256>>>(
            xnorm, D_MODEL, W_in, 2 * E_INNER, xz, 2 * E_INNER,
            NTOK, 2 * E_INNER, D_MODEL, nullptr, nullptr, 0);
    }

    // 3. causal dwconv + SiLU
    {
        dim3 g(E_INNER / 256, SEQ / 64, BATCH);
        conv_silu_kernel<<<g, 256>>>(xz, conv_w, xact);
    }

    // 4. GEMM2: xdb = xact @ W_x    [4096,2048]x[2048,160]
    {
        dim3 g((XDB_W + 63) / 64, NTOK / 64);
        gemm_kernel<64,64,16,4,4,0><<<g, 256>>>(
            xact, E_INNER, W_x, XDB_W, xdb, XDB_W,
            NTOK, XDB_W, E_INNER, nullptr, nullptr, 0);
    }

    // 5. GEMM3: delta = softplus(xdb[:, :64] @ W_dt + b_dt)  [4096,64]x[64,2048]
    {
        dim3 g(E_INNER / 128, NTOK / 128);
        gemm_kernel<128,128,8,8,8,1><<<g, 256>>>(
            xdb, XDB_W, W_dt, E_INNER, delta, E_INNER,
            NTOK, E_INNER, DT_RANK, b_dt, nullptr, 0);
    }

    // 6. selective scan + gate; also writes h_last into tail of d_out
    scan_kernel<<<(BATCH * E_INNER * N_STATE) / 256, 256>>>(
        xz, xact, delta, xdb, A_log, D_param, y, hlast);

    // 7. GEMM4: out = residual + y @ W_out  [4096,2048]x[2048,1024]
    {
        dim3 g(D_MODEL / 128, NTOK / 128);
        gemm_kernel<128,128,8,8,8,2><<<g, 256>>>(
            y, E_INNER, W_out, D_MODEL, out, D_MODEL,
            NTOK, D_MODEL, E_INNER, nullptr, hidden, D_MODEL);
    }
}

// round 10
// speedup vs baseline: 1.5290x; 1.5290x over previous
#include <cuda_runtime.h>
#include <cuda_bf16.h>
#include <math.h>
#include <stdint.h>

#define D_MODEL 1024
#define N_STATE 16
#define E_INNER 2048
#define K_CONV  4
#define DT_RANK 64
#define BATCH   4
#define SEQ     1024
#define NTOK    (BATCH*SEQ)           // 4096
#define XDB_W   (DT_RANK + 2*N_STATE) // 160

// ---------------- scratch (device globals: allocation-free) ----------------
__device__ float g_xz   [(size_t)NTOK * 2 * E_INNER];    // 64 MB
__device__ float g_xact [(size_t)NTOK * E_INNER];        // 32 MB
__device__ float g_xdb  [(size_t)NTOK * XDB_W];          // 2.6 MB
__device__ float g_delta[(size_t)NTOK * E_INNER];        // 32 MB

__device__ __nv_bfloat16 g_xnh [(size_t)NTOK * D_MODEL];        // 8 MB
__device__ __nv_bfloat16 g_xnl [(size_t)NTOK * D_MODEL];        // 8 MB
__device__ __nv_bfloat16 g_winh[(size_t)(2*E_INNER) * D_MODEL]; // 8 MB  (W_in^T)
__device__ __nv_bfloat16 g_winl[(size_t)(2*E_INNER) * D_MODEL]; // 8 MB
__device__ __nv_bfloat16 g_yh  [(size_t)NTOK * E_INNER];        // 16 MB
__device__ __nv_bfloat16 g_yl  [(size_t)NTOK * E_INNER];        // 16 MB
__device__ __nv_bfloat16 g_woth[(size_t)D_MODEL * E_INNER];     // 4 MB   (W_out^T)
__device__ __nv_bfloat16 g_wotl[(size_t)D_MODEL * E_INNER];     // 4 MB
__device__ __nv_bfloat16 g_xah [(size_t)NTOK * E_INNER];        // 16 MB
__device__ __nv_bfloat16 g_xal [(size_t)NTOK * E_INNER];        // 16 MB
__device__ __nv_bfloat16 g_wxh [(size_t)XDB_W * E_INNER];       // 0.64 MB (W_x^T)
__device__ __nv_bfloat16 g_wxl [(size_t)XDB_W * E_INNER];       // 0.64 MB
__device__ __nv_bfloat16 g_wdth[(size_t)E_INNER * DT_RANK];     // 0.25 MB (W_dt^T)
__device__ __nv_bfloat16 g_wdtl[(size_t)E_INNER * DT_RANK];     // 0.25 MB
__device__ __nv_bfloat16 g_dth [(size_t)NTOK * DT_RANK];        // 0.5 MB
__device__ __nv_bfloat16 g_dtl [(size_t)NTOK * DT_RANK];        // 0.5 MB

// ================= PTX helpers (baseline sm_80+ instructions only) =================
__device__ __forceinline__ uint32_t smem_u32(const void* p) {
    uint32_t a;
    asm("{ .reg .u64 t; cvta.to.shared.u64 t, %1; cvt.u32.u64 %0, t; }"
        : "=r"(a) : "l"(p));
    return a;
}
__device__ __forceinline__ void cp_async16(uint32_t dst, const void* src, int bytes) {
    asm volatile("cp.async.cg.shared.global [%0], [%1], 16, %2;"
                 :: "r"(dst), "l"(src), "r"(bytes) : "memory");
}
#define CP_COMMIT() asm volatile("cp.async.commit_group;" ::: "memory")
#define CP_WAIT(n)  asm volatile("cp.async.wait_group %0;" :: "n"(n) : "memory")

__device__ __forceinline__ void ldmx4(uint32_t& r0, uint32_t& r1,
                                      uint32_t& r2, uint32_t& r3, uint32_t addr) {
    asm volatile("ldmatrix.sync.aligned.m8n8.x4.shared.b16 {%0,%1,%2,%3}, [%4];"
                 : "=r"(r0), "=r"(r1), "=r"(r2), "=r"(r3) : "r"(addr));
}
__device__ __forceinline__ void mma_bf16(float* d, const uint32_t* a, const uint32_t* b) {
    asm volatile("mma.sync.aligned.m16n8k16.row.col.f32.bf16.bf16.f32 "
                 "{%0,%1,%2,%3}, {%4,%5,%6,%7}, {%8,%9}, {%0,%1,%2,%3};"
                 : "+f"(d[0]), "+f"(d[1]), "+f"(d[2]), "+f"(d[3])
                 : "r"(a[0]), "r"(a[1]), "r"(a[2]), "r"(a[3]),
                   "r"(b[0]), "r"(b[1]));
}

// ---------------- RMSNorm -> bf16 hi/lo split ----------------
__global__ void rmsnorm_kernel(const float* __restrict__ x,
                               const float* __restrict__ w,
                               __nv_bfloat16* __restrict__ oh,
                               __nv_bfloat16* __restrict__ ol) {
    int t   = blockIdx.x;
    int tid = threadIdx.x;         // 256 threads, 4 floats each
    const float4* xr = reinterpret_cast<const float4*>(x) + (size_t)t * (D_MODEL / 4);
    float4 xv = xr[tid];
    float s = xv.x*xv.x + xv.y*xv.y + xv.z*xv.z + xv.w*xv.w;
    #pragma unroll
    for (int o = 16; o > 0; o >>= 1) s += __shfl_xor_sync(0xffffffffu, s, o);
    __shared__ float red[8];
    if ((tid & 31) == 0) red[tid >> 5] = s;
    __syncthreads();
    if (tid == 0) {
        float tot = 0.f;
        #pragma unroll
        for (int i = 0; i < 8; i++) tot += red[i];
        red[0] = tot;
    }
    __syncthreads();
    float r = rsqrtf(red[0] * (1.0f / D_MODEL) + 1e-6f);
    float4 wv = reinterpret_cast<const float4*>(w)[tid];
    float v[4] = { xv.x * r * wv.x, xv.y * r * wv.y, xv.z * r * wv.z, xv.w * r * wv.w };
    __nv_bfloat162* ohp = reinterpret_cast<__nv_bfloat162*>(oh) + (size_t)t * (D_MODEL / 2);
    __nv_bfloat162* olp = reinterpret_cast<__nv_bfloat162*>(ol) + (size_t)t * (D_MODEL / 2);
    float h0 = __bfloat162float(__float2bfloat16_rn(v[0]));
    float h1 = __bfloat162float(__float2bfloat16_rn(v[1]));
    float h2 = __bfloat162float(__float2bfloat16_rn(v[2]));
    float h3 = __bfloat162float(__float2bfloat16_rn(v[3]));
    ohp[tid*2+0] = __floats2bfloat162_rn(h0, h1);
    ohp[tid*2+1] = __floats2bfloat162_rn(h2, h3);
    olp[tid*2+0] = __floats2bfloat162_rn(v[0]-h0, v[1]-h1);
    olp[tid*2+1] = __floats2bfloat162_rn(v[2]-h2, v[3]-h3);
}

// ---------------- weight transpose + bf16 split: W[K,N] -> T[N,K] ----------------
__global__ void transpose_split_kernel(const float* __restrict__ W, int K, int N,
                                       __nv_bfloat16* __restrict__ Th,
                                       __nv_bfloat16* __restrict__ Tl) {
    __shared__ float t[32][33];
    int n0 = blockIdx.x * 32, k0 = blockIdx.y * 32;
    int tx = threadIdx.x, ty = threadIdx.y;      // 32 x 8
    #pragma unroll
    for (int i = 0; i < 32; i += 8) {
        int kk = k0 + ty + i, nn = n0 + tx;
        t[ty + i][tx] = (kk < K && nn < N) ? W[(size_t)kk * N + nn] : 0.f;
    }
    __syncthreads();
    #pragma unroll
    for (int i = 0; i < 32; i += 8) {
        int nn = n0 + ty + i, kk = k0 + tx;
        if (nn < N && kk < K) {
            float v = t[tx][ty + i];
            __nv_bfloat16 h = __float2bfloat16_rn(v);
            float lo = v - __bfloat162float(h);
            size_t o = (size_t)nn * K + kk;
            Th[o] = h;
            Tl[o] = __float2bfloat16_rn(lo);
        }
    }
}

// ---------------- dt_lr split: xdb[:, :64] -> bf16 hi/lo ----------------
__global__ void dt_split_kernel(const float* __restrict__ xdb,
                                __nv_bfloat16* __restrict__ dth,
                                __nv_bfloat16* __restrict__ dtl) {
    int t = blockIdx.x;
    int c = threadIdx.x;     // 64
    float v = xdb[(size_t)t * XDB_W + c];
    __nv_bfloat16 h = __float2bfloat16_rn(v);
    dth[(size_t)t * DT_RANK + c] = h;
    dtl[(size_t)t * DT_RANK + c] = __float2bfloat16_rn(v - __bfloat162float(h));
}

// ================ bf16 mma.sync GEMM (2-term split, 3 MMAs) ================
// C[M,N] = A[M,K] @ B[N,K]^T, A/B given as hi/lo bf16 row-major (K-major).
// CTA 128x128, BK=32, 8 warps (warp tile 32x64), double-buffered cp.async.
// EPI: 0 plain, 1 softplus(acc + aux[col]), 2 acc + aux[r*N+col] (residual)
#define MM_TSTRIDE_B 80          // 40 bf16 per row (32 + 8 pad)
#define MM_TILE_B    (128 * MM_TSTRIDE_B)   // 10240
#define MM_STAGE_B   (4 * MM_TILE_B)        // 40960
#define MM_SMEM_B    (2 * MM_STAGE_B)       // 81920

__device__ __forceinline__ void mm_load_chunk(
    const __nv_bfloat16* __restrict__ Ah, const __nv_bfloat16* __restrict__ Al,
    const __nv_bfloat16* __restrict__ Bh, const __nv_bfloat16* __restrict__ Bl,
    int K, int row0, int col0, int k0, int brows,
    uint32_t sbase, int tid) {
    #pragma unroll
    for (int i = 0; i < 2; i++) {
        int u = tid + i * 256;
        int r = u >> 2, c = u & 3;
        uint32_t sm = sbase + r * MM_TSTRIDE_B + c * 16;
        size_t aoff = (size_t)(row0 + r) * K + k0 + c * 8;
        cp_async16(sm,              Ah + aoff, 16);
        cp_async16(sm + MM_TILE_B,  Al + aoff, 16);
        int gbr = col0 + r;
        int bbytes = (gbr < brows) ? 16 : 0;
        int gbc = (gbr < brows) ? gbr : (brows - 1);
        size_t boff = (size_t)gbc * K + k0 + c * 8;
        cp_async16(sm + 2*MM_TILE_B, Bh + boff, bbytes);
        cp_async16(sm + 3*MM_TILE_B, Bl + boff, bbytes);
    }
}

__global__ __launch_bounds__(256)
void gemm_mma_kernel(const __nv_bfloat16* __restrict__ Ah,
                     const __nv_bfloat16* __restrict__ Al,
                     const __nv_bfloat16* __restrict__ Bh,
                     const __nv_bfloat16* __restrict__ Bl,
                     float* __restrict__ C,
                     const float* __restrict__ aux,
                     int N, int K, int brows, int EPI) {
    extern __shared__ __align__(128) char sm[];
    uint32_t sm0 = smem_u32(sm);

    int tid = threadIdx.x;
    int wid = tid >> 5, lane = tid & 31;
    int wy = wid >> 1, wx = wid & 1;            // 4 x 2 warps
    int row0 = blockIdx.y * 128, col0 = blockIdx.x * 128;

    float acc[2][8][4];
    #pragma unroll
    for (int mt = 0; mt < 2; mt++)
        #pragma unroll
        for (int nt = 0; nt < 8; nt++)
            #pragma unroll
            for (int q = 0; q < 4; q++) acc[mt][nt][q] = 0.f;

    const int NC = K / 32;

    // prologue: chunk 0 -> slot 0
    mm_load_chunk(Ah, Al, Bh, Bl, K, row0, col0, 0, brows, sm0, tid);
    CP_COMMIT();

    // frag address components
    int arow = lane & 15;
    int acolb0 = ((lane >> 4) * 8) * 2;
    int brow = (lane & 7) + ((lane >> 4) << 3);
    int bcolb0 = (((lane >> 3) & 1) * 8) * 2;

    for (int c = 0; c < NC; c++) {
        if (c + 1 < NC) {
            mm_load_chunk(Ah, Al, Bh, Bl, K, row0, col0, (c + 1) * 32, brows,
                          sm0 + ((c + 1) & 1) * MM_STAGE_B, tid);
            CP_COMMIT();
            CP_WAIT(1);
        } else {
            CP_WAIT(0);
        }
        __syncthreads();

        uint32_t sb = sm0 + (c & 1) * MM_STAGE_B;
        #pragma unroll
        for (int ks = 0; ks < 2; ks++) {
            uint32_t aAh[2][4], aAl[2][4];
            int acol = ks * 32 + acolb0;
            #pragma unroll
            for (int mt = 0; mt < 2; mt++) {
                uint32_t ad = sb + (wy * 32 + mt * 16 + arow) * MM_TSTRIDE_B + acol;
                ldmx4(aAh[mt][0], aAh[mt][1], aAh[mt][2], aAh[mt][3], ad);
                ldmx4(aAl[mt][0], aAl[mt][1], aAl[mt][2], aAl[mt][3], ad + MM_TILE_B);
            }
            uint32_t bF[8][2];
            int bcol = ks * 32 + bcolb0;
            #pragma unroll
            for (int nt2 = 0; nt2 < 4; nt2++) {
                uint32_t bd = sb + 2*MM_TILE_B
                            + (wx * 64 + nt2 * 16 + brow) * MM_TSTRIDE_B + bcol;
                uint32_t r0, r1, r2, r3;
                ldmx4(r0, r1, r2, r3, bd);
                bF[nt2*2][0] = r0; bF[nt2*2][1] = r1;
                bF[nt2*2+1][0] = r2; bF[nt2*2+1][1] = r3;
            }
            #pragma unroll
            for (int mt = 0; mt < 2; mt++)
                #pragma unroll
                for (int nt = 0; nt < 8; nt++) {
                    mma_bf16(acc[mt][nt], aAh[mt], bF[nt]);   // Ah*Bh
                    mma_bf16(acc[mt][nt], aAl[mt], bF[nt]);   // Al*Bh
                }
            #pragma unroll
            for (int nt2 = 0; nt2 < 4; nt2++) {
                uint32_t bd = sb + 3*MM_TILE_B
                            + (wx * 64 + nt2 * 16 + brow) * MM_TSTRIDE_B + bcol;
                uint32_t r0, r1, r2, r3;
                ldmx4(r0, r1, r2, r3, bd);
                bF[nt2*2][0] = r0; bF[nt2*2][1] = r1;
                bF[nt2*2+1][0] = r2; bF[nt2*2+1][1] = r3;
            }
            #pragma unroll
            for (int mt = 0; mt < 2; mt++)
                #pragma unroll
                for (int nt = 0; nt < 8; nt++)
                    mma_bf16(acc[mt][nt], aAh[mt], bF[nt]);   // Ah*Bl
        }
        __syncthreads();
    }

    // epilogue
    int r_base = row0 + wy * 32 + (lane >> 2);
    int c_base = col0 + wx * 64 + (lane & 3) * 2;
    #pragma unroll
    for (int mt = 0; mt < 2; mt++) {
        #pragma unroll
        for (int half = 0; half < 2; half++) {
            int r = r_base + mt * 16 + half * 8;
            #pragma unroll
            for (int nt = 0; nt < 8; nt++) {
                int cc = c_base + nt * 8;
                if (cc < N) {
                    float2 v = make_float2(acc[mt][nt][half*2], acc[mt][nt][half*2+1]);
                    if (EPI == 1) {
                        v.x += aux[cc]; v.y += aux[cc + 1];
                        v.x = (v.x > 20.f) ? v.x : log1pf(__expf(v.x));
                        v.y = (v.y > 20.f) ? v.y : log1pf(__expf(v.y));
                    } else if (EPI == 2) {
                        float2 a = *reinterpret_cast<const float2*>(
                            aux + (size_t)r * N + cc);
                        v.x += a.x; v.y += a.y;
                    }
                    *reinterpret_cast<float2*>(C + (size_t)r * N + cc) = v;
                }
            }
        }
    }
}

// ---------------- causal depthwise conv (K=4) + SiLU (fp32 + bf16 hi/lo) ----------------
__global__ void conv_silu_kernel(const float* __restrict__ xz,
                                 const float* __restrict__ conv_w,
                                 float* __restrict__ xact,
                                 __nv_bfloat16* __restrict__ xah,
                                 __nv_bfloat16* __restrict__ xal) {
    int e  = blockIdx.x * blockDim.x + threadIdx.x;
    int l0 = blockIdx.y * 64;
    int b  = blockIdx.z;
    float w0 = conv_w[e * 4 + 0];
    float w1 = conv_w[e * 4 + 1];
    float w2 = conv_w[e * 4 + 2];
    float w3 = conv_w[e * 4 + 3];
    float x0 = 0.f, x1 = 0.f, x2 = 0.f;
    #pragma unroll
    for (int j = -3; j < 0; j++) {
        int l = l0 + j;
        float v = (l >= 0) ? xz[((size_t)(b * SEQ + l)) * (2 * E_INNER) + e] : 0.f;
        x0 = x1; x1 = x2; x2 = v;
    }
    for (int i = 0; i < 64; i++) {
        int l = l0 + i;
        float x3 = xz[((size_t)(b * SEQ + l)) * (2 * E_INNER) + e];
        float s = w0 * x0 + w1 * x1 + w2 * x2 + w3 * x3;
        s = s / (1.f + __expf(-s));
        size_t idx = ((size_t)(b * SEQ + l)) * E_INNER + e;
        xact[idx] = s;
        __nv_bfloat16 h = __float2bfloat16_rn(s);
        xah[idx] = h;
        xal[idx] = __float2bfloat16_rn(s - __bfloat162float(h));
        x0 = x1; x1 = x2; x2 = x3;
    }
}

// ---------------- selective scan + gate -> y (bf16 hi/lo) + h_last ----------------
__global__ void scan_kernel(const float* __restrict__ xz,
                            const float* __restrict__ xact,
                            const float* __restrict__ delta,
                            const float* __restrict__ xdb,
                            const float* __restrict__ A_log,
                            const float* __restrict__ D_param,
                            __nv_bfloat16* __restrict__ yh,
                            __nv_bfloat16* __restrict__ yl,
                            float* __restrict__ hlast) {
    int gid = blockIdx.x * blockDim.x + threadIdx.x;
    int c = gid >> 4;
    int n = gid & 15;
    int b = c >> 11;
    int e = c & (E_INNER - 1);

    float An = -__expf(A_log[e * N_STATE + n]);
    float Dp = D_param[e];
    float h = 0.f;

    size_t tok = (size_t)b * SEQ;
    for (int l = 0; l < SEQ; l++) {
        size_t row = tok + l;
        float dlt = delta[row * E_INNER + e];
        float u   = xact [row * E_INNER + e];
        float Bv  = xdb[row * XDB_W + DT_RANK + n];
        float Cv  = xdb[row * XDB_W + DT_RANK + N_STATE + n];
        float dA  = __expf(dlt * An);
        h = fmaf(dA, h, dlt * u * Bv);
        float p = h * Cv;
        p += __shfl_xor_sync(0xffffffffu, p, 1, 16);
        p += __shfl_xor_sync(0xffffffffu, p, 2, 16);
        p += __shfl_xor_sync(0xffffffffu, p, 4, 16);
        p += __shfl_xor_sync(0xffffffffu, p, 8, 16);
        if (n == 0) {
            float zv = xz[row * (2 * E_INNER) + E_INNER + e];
            float yv = (p + u * Dp) * (zv / (1.f + __expf(-zv)));
            __nv_bfloat16 hi = __float2bfloat16_rn(yv);
            yh[row * E_INNER + e] = hi;
            yl[row * E_INNER + e] = __float2bfloat16_rn(yv - __bfloat162float(hi));
        }
    }
    hlast[(size_t)c * N_STATE + n] = h;
}

// ---------------- launch ----------------
extern "C" void kernel_launch(void* const* d_in, const int* in_sizes, int n_in,
                              void* d_out, int out_size) {
    const float* hidden  = (const float*)d_in[0];
    const float* norm_w  = (const float*)d_in[1];
    const float* W_in    = (const float*)d_in[2];
    const float* conv_w  = (const float*)d_in[3];
    const float* W_x     = (const float*)d_in[4];
    const float* W_dt    = (const float*)d_in[5];
    const float* b_dt    = (const float*)d_in[6];
    const float* A_log   = (const float*)d_in[7];
    const float* D_param = (const float*)d_in[8];
    const float* W_out   = (const float*)d_in[9];

    float* out   = (float*)d_out;
    float* hlast = out + (size_t)NTOK * D_MODEL;

    float *xz, *xact, *xdb, *delta;
    __nv_bfloat16 *xnh, *xnl, *winh, *winl, *yh, *yl, *woth, *wotl;
    __nv_bfloat16 *xah, *xal, *wxh, *wxl, *wdth, *wdtl, *dth, *dtl;
    cudaGetSymbolAddress((void**)&xz,    g_xz);
    cudaGetSymbolAddress((void**)&xact,  g_xact);
    cudaGetSymbolAddress((void**)&xdb,   g_xdb);
    cudaGetSymbolAddress((void**)&delta, g_delta);
    cudaGetSymbolAddress((void**)&xnh,   g_xnh);
    cudaGetSymbolAddress((void**)&xnl,   g_xnl);
    cudaGetSymbolAddress((void**)&winh,  g_winh);
    cudaGetSymbolAddress((void**)&winl,  g_winl);
    cudaGetSymbolAddress((void**)&yh,    g_yh);
    cudaGetSymbolAddress((void**)&yl,    g_yl);
    cudaGetSymbolAddress((void**)&woth,  g_woth);
    cudaGetSymbolAddress((void**)&wotl,  g_wotl);
    cudaGetSymbolAddress((void**)&xah,   g_xah);
    cudaGetSymbolAddress((void**)&xal,   g_xal);
    cudaGetSymbolAddress((void**)&wxh,   g_wxh);
    cudaGetSymbolAddress((void**)&wxl,   g_wxl);
    cudaGetSymbolAddress((void**)&wdth,  g_wdth);
    cudaGetSymbolAddress((void**)&wdtl,  g_wdtl);
    cudaGetSymbolAddress((void**)&dth,   g_dth);
    cudaGetSymbolAddress((void**)&dtl,   g_dtl);

    cudaFuncSetAttribute(gemm_mma_kernel,
                         cudaFuncAttributeMaxDynamicSharedMemorySize, MM_SMEM_B);

    // 0. weight transposes + bf16 splits (cheap, parallel)
    {
        dim3 b(32, 8);
        transpose_split_kernel<<<dim3(2*E_INNER/32, D_MODEL/32), b>>>(
            W_in, D_MODEL, 2*E_INNER, winh, winl);
        transpose_split_kernel<<<dim3(D_MODEL/32, E_INNER/32), b>>>(
            W_out, E_INNER, D_MODEL, woth, wotl);
        transpose_split_kernel<<<dim3((XDB_W + 31)/32, E_INNER/32), b>>>(
            W_x, E_INNER, XDB_W, wxh, wxl);
        transpose_split_kernel<<<dim3(E_INNER/32, DT_RANK/32), b>>>(
            W_dt, DT_RANK, E_INNER, wdth, wdtl);
    }

    // 1. RMSNorm -> bf16 split
    rmsnorm_kernel<<<NTOK, 256>>>(hidden, norm_w, xnh, xnl);

    // 2. GEMM1 (mma): xz = xnorm @ W_in   [4096,1024]x[1024,4096]
    gemm_mma_kernel<<<dim3(2*E_INNER/128, NTOK/128), 256, MM_SMEM_B>>>(
        xnh, xnl, winh, winl, xz, nullptr, 2*E_INNER, D_MODEL, 2*E_INNER, 0);

    // 3. causal dwconv + SiLU -> xact fp32 + bf16 split
    conv_silu_kernel<<<dim3(E_INNER/256, SEQ/64, BATCH), 256>>>(
        xz, conv_w, xact, xah, xal);

    // 4. GEMM2 (mma): xdb = xact @ W_x   [4096,2048]x[2048,160]
    gemm_mma_kernel<<<dim3((XDB_W + 127)/128, NTOK/128), 256, MM_SMEM_B>>>(
        xah, xal, wxh, wxl, xdb, nullptr, XDB_W, E_INNER, XDB_W, 0);

    // 5a. split dt_lr -> bf16 hi/lo
    dt_split_kernel<<<NTOK, DT_RANK>>>(xdb, dth, dtl);

    // 5b. GEMM3 (mma): delta = softplus(dt_lr @ W_dt + b_dt)  [4096,64]x[64,2048]
    gemm_mma_kernel<<<dim3(E_INNER/128, NTOK/128), 256, MM_SMEM_B>>>(
        dth, dtl, wdth, wdtl, delta, b_dt, E_INNER, DT_RANK, E_INNER, 1);

    // 6. selective scan + gate -> y (bf16 split), h_last
    scan_kernel<<<(BATCH * E_INNER * N_STATE) / 256, 256>>>(
        xz, xact, delta, xdb, A_log, D_param, yh, yl, hlast);

    // 7. GEMM4 (mma): out = residual + y @ W_out  [4096,2048]x[2048,1024]
    gemm_mma_kernel<<<dim3(D_MODEL/128, NTOK/128), 256, MM_SMEM_B>>>(
        yh, yl, woth, wotl, out, hidden, D_MODEL, E_INNER, D_MODEL, 2);
}

// round 11
// speedup vs baseline: 1.7203x; 1.1251x over previous
#include <cuda_runtime.h>
#include <cuda_fp16.h>
#include <math.h>
#include <stdint.h>

#define D_MODEL 1024
#define N_STATE 16
#define E_INNER 2048
#define K_CONV  4
#define DT_RANK 64
#define BATCH   4
#define SEQ     1024
#define NTOK    (BATCH*SEQ)           // 4096
#define XDB_W   (DT_RANK + 2*N_STATE) // 160

// ---------------- scratch (device globals: allocation-free) ----------------
__device__ float g_xz   [(size_t)NTOK * 2 * E_INNER];    // 64 MB
__device__ float g_xact [(size_t)NTOK * E_INNER];        // 32 MB
__device__ float g_xdb  [(size_t)NTOK * XDB_W];          // 2.6 MB
__device__ float g_delta[(size_t)NTOK * E_INNER];        // 32 MB

__device__ __half g_xnh [(size_t)NTOK * D_MODEL];        // 8 MB
__device__ __half g_winh[(size_t)(2*E_INNER) * D_MODEL]; // 8 MB  (W_in^T hi)
__device__ __half g_winl[(size_t)(2*E_INNER) * D_MODEL]; // 8 MB  (W_in^T lo)
__device__ __half g_yh  [(size_t)NTOK * E_INNER];        // 16 MB
__device__ __half g_woth[(size_t)D_MODEL * E_INNER];     // 4 MB   (W_out^T hi)
__device__ __half g_wotl[(size_t)D_MODEL * E_INNER];     // 4 MB   (W_out^T lo)
__device__ __half g_xah [(size_t)NTOK * E_INNER];        // 16 MB
__device__ __half g_wxh [(size_t)XDB_W * E_INNER];       // 0.64 MB (W_x^T hi)
__device__ __half g_wxl [(size_t)XDB_W * E_INNER];       // 0.64 MB
__device__ __half g_wdth[(size_t)E_INNER * DT_RANK];     // 0.25 MB (W_dt^T hi)
__device__ __half g_wdtl[(size_t)E_INNER * DT_RANK];     // 0.25 MB
__device__ __half g_dth [(size_t)NTOK * DT_RANK];        // 0.5 MB

// ================= PTX helpers (baseline sm_80+ instructions only) =================
__device__ __forceinline__ uint32_t smem_u32(const void* p) {
    uint32_t a;
    asm("{ .reg .u64 t; cvta.to.shared.u64 t, %1; cvt.u32.u64 %0, t; }"
        : "=r"(a) : "l"(p));
    return a;
}
__device__ __forceinline__ void cp_async16(uint32_t dst, const void* src, int bytes) {
    asm volatile("cp.async.cg.shared.global [%0], [%1], 16, %2;"
                 :: "r"(dst), "l"(src), "r"(bytes) : "memory");
}
#define CP_COMMIT() asm volatile("cp.async.commit_group;" ::: "memory")
#define CP_WAIT(n)  asm volatile("cp.async.wait_group %0;" :: "n"(n) : "memory")

__device__ __forceinline__ void ldmx4(uint32_t& r0, uint32_t& r1,
                                      uint32_t& r2, uint32_t& r3, uint32_t addr) {
    asm volatile("ldmatrix.sync.aligned.m8n8.x4.shared.b16 {%0,%1,%2,%3}, [%4];"
                 : "=r"(r0), "=r"(r1), "=r"(r2), "=r"(r3) : "r"(addr));
}
__device__ __forceinline__ void mma_fp16(float* d, const uint32_t* a, const uint32_t* b) {
    asm volatile("mma.sync.aligned.m16n8k16.row.col.f32.f16.f16.f32 "
                 "{%0,%1,%2,%3}, {%4,%5,%6,%7}, {%8,%9}, {%0,%1,%2,%3};"
                 : "+f"(d[0]), "+f"(d[1]), "+f"(d[2]), "+f"(d[3])
                 : "r"(a[0]), "r"(a[1]), "r"(a[2]), "r"(a[3]),
                   "r"(b[0]), "r"(b[1]));
}

// ---------------- RMSNorm -> fp16 (single rounding) ----------------
__global__ void rmsnorm_kernel(const float* __restrict__ x,
                               const float* __restrict__ w,
                               __half* __restrict__ oh) {
    int t   = blockIdx.x;
    int tid = threadIdx.x;         // 256 threads, 4 floats each
    const float4* xr = reinterpret_cast<const float4*>(x) + (size_t)t * (D_MODEL / 4);
    float4 xv = xr[tid];
    float s = xv.x*xv.x + xv.y*xv.y + xv.z*xv.z + xv.w*xv.w;
    #pragma unroll
    for (int o = 16; o > 0; o >>= 1) s += __shfl_xor_sync(0xffffffffu, s, o);
    __shared__ float red[8];
    if ((tid & 31) == 0) red[tid >> 5] = s;
    __syncthreads();
    if (tid == 0) {
        float tot = 0.f;
        #pragma unroll
        for (int i = 0; i < 8; i++) tot += red[i];
        red[0] = tot;
    }
    __syncthreads();
    float r = rsqrtf(red[0] * (1.0f / D_MODEL) + 1e-6f);
    float4 wv = reinterpret_cast<const float4*>(w)[tid];
    __half2* ohp = reinterpret_cast<__half2*>(oh) + (size_t)t * (D_MODEL / 2);
    ohp[tid*2+0] = __floats2half2_rn(xv.x * r * wv.x, xv.y * r * wv.y);
    ohp[tid*2+1] = __floats2half2_rn(xv.z * r * wv.z, xv.w * r * wv.w);
}

// ---------------- weight transpose + fp16 hi/lo split: W[K,N] -> T[N,K] ----------------
__global__ void transpose_split_kernel(const float* __restrict__ W, int K, int N,
                                       __half* __restrict__ Th,
                                       __half* __restrict__ Tl) {
    __shared__ float t[32][33];
    int n0 = blockIdx.x * 32, k0 = blockIdx.y * 32;
    int tx = threadIdx.x, ty = threadIdx.y;      // 32 x 8
    #pragma unroll
    for (int i = 0; i < 32; i += 8) {
        int kk = k0 + ty + i, nn = n0 + tx;
        t[ty + i][tx] = (kk < K && nn < N) ? W[(size_t)kk * N + nn] : 0.f;
    }
    __syncthreads();
    #pragma unroll
    for (int i = 0; i < 32; i += 8) {
        int nn = n0 + ty + i, kk = k0 + tx;
        if (nn < N && kk < K) {
            float v = t[tx][ty + i];
            __half h = __float2half_rn(v);
            float lo = v - __half2float(h);
            size_t o = (size_t)nn * K + kk;
            Th[o] = h;
            Tl[o] = __float2half_rn(lo);
        }
    }
}

// ---------------- dt_lr -> fp16: xdb[:, :64] ----------------
__global__ void dt_split_kernel(const float* __restrict__ xdb,
                                __half* __restrict__ dth) {
    int t = blockIdx.x;
    int c = threadIdx.x;     // 64
    dth[(size_t)t * DT_RANK + c] = __float2half_rn(xdb[(size_t)t * XDB_W + c]);
}

// ================ fp16 mma.sync GEMM (A single, B hi/lo: 2 MMAs) ================
// C[M,N] = A[M,K] @ B[N,K]^T; A single-rounded fp16, B split hi/lo fp16, K-major.
// CTA 128x128, BK=32, 8 warps (warp tile 32x64), 3-stage cp.async pipeline.
// EPI: 0 plain, 1 softplus(acc + aux[col]), 2 acc + aux[r*N+col] (residual)
#define MM_TSTRIDE_B 80                    // 32 fp16 (64B) + 16B pad
#define MM_TILE_B    (128 * MM_TSTRIDE_B)  // 10240
#define MM_STAGE_B   (3 * MM_TILE_B)       // 30720  (A, Bh, Bl)
#define MM_SMEM_B    (3 * MM_STAGE_B)      // 92160

__device__ __forceinline__ void mm_load_chunk(
    const __half* __restrict__ A,
    const __half* __restrict__ Bh, const __half* __restrict__ Bl,
    int K, int row0, int col0, int k0, int brows,
    uint32_t sbase, int tid) {
    #pragma unroll
    for (int i = 0; i < 2; i++) {
        int u = tid + i * 256;
        int r = u >> 2, c = u & 3;
        uint32_t sm = sbase + r * MM_TSTRIDE_B + c * 16;
        cp_async16(sm, A + (size_t)(row0 + r) * K + k0 + c * 8, 16);
        int gbr = col0 + r;
        int bbytes = (gbr < brows) ? 16 : 0;
        int gbc = (gbr < brows) ? gbr : 0;
        size_t boff = (size_t)gbc * K + k0 + c * 8;
        cp_async16(sm + MM_TILE_B,     Bh + boff, bbytes);
        cp_async16(sm + 2*MM_TILE_B,   Bl + boff, bbytes);
    }
}

__global__ __launch_bounds__(256)
void gemm_mma_kernel(const __half* __restrict__ A,
                     const __half* __restrict__ Bh,
                     const __half* __restrict__ Bl,
                     float* __restrict__ C,
                     const float* __restrict__ aux,
                     int N, int K, int brows, int EPI) {
    extern __shared__ __align__(128) char sm[];
    uint32_t sm0 = smem_u32(sm);

    int tid = threadIdx.x;
    int wid = tid >> 5, lane = tid & 31;
    int wy = wid >> 1, wx = wid & 1;            // 4 x 2 warps
    int row0 = blockIdx.y * 128, col0 = blockIdx.x * 128;

    float acc[2][8][4];
    #pragma unroll
    for (int mt = 0; mt < 2; mt++)
        #pragma unroll
        for (int nt = 0; nt < 8; nt++)
            #pragma unroll
            for (int q = 0; q < 4; q++) acc[mt][nt][q] = 0.f;

    const int NC = K / 32;

    // prologue: 2 stages in flight
    mm_load_chunk(A, Bh, Bl, K, row0, col0, 0, brows, sm0, tid);
    CP_COMMIT();
    if (NC > 1) {
        mm_load_chunk(A, Bh, Bl, K, row0, col0, 32, brows, sm0 + MM_STAGE_B, tid);
        CP_COMMIT();
    }

    // frag address components
    int arow = lane & 15;
    int acolb0 = ((lane >> 4) * 8) * 2;
    int brow = (lane & 7) + ((lane >> 4) << 3);
    int bcolb0 = (((lane >> 3) & 1) * 8) * 2;

    for (int c = 0; c < NC; c++) {
        if (c + 2 < NC) {
            mm_load_chunk(A, Bh, Bl, K, row0, col0, (c + 2) * 32, brows,
                          sm0 + ((c + 2) % 3) * MM_STAGE_B, tid);
            CP_COMMIT();
            CP_WAIT(2);
        } else if (c + 1 < NC) {
            CP_WAIT(1);
        } else {
            CP_WAIT(0);
        }
        __syncthreads();

        uint32_t sb = sm0 + (c % 3) * MM_STAGE_B;
        #pragma unroll
        for (int ks = 0; ks < 2; ks++) {
            uint32_t aF[2][4];
            int acol = ks * 32 + acolb0;
            #pragma unroll
            for (int mt = 0; mt < 2; mt++) {
                uint32_t ad = sb + (wy * 32 + mt * 16 + arow) * MM_TSTRIDE_B + acol;
                ldmx4(aF[mt][0], aF[mt][1], aF[mt][2], aF[mt][3], ad);
            }
            uint32_t bF[8][2];
            int bcol = ks * 32 + bcolb0;
            #pragma unroll
            for (int nt2 = 0; nt2 < 4; nt2++) {
                uint32_t bd = sb + MM_TILE_B
                            + (wx * 64 + nt2 * 16 + brow) * MM_TSTRIDE_B + bcol;
                uint32_t r0, r1, r2, r3;
                ldmx4(r0, r1, r2, r3, bd);
                bF[nt2*2][0] = r0; bF[nt2*2][1] = r1;
                bF[nt2*2+1][0] = r2; bF[nt2*2+1][1] = r3;
            }
            #pragma unroll
            for (int mt = 0; mt < 2; mt++)
                #pragma unroll
                for (int nt = 0; nt < 8; nt++)
                    mma_fp16(acc[mt][nt], aF[mt], bF[nt]);    // A*Bh
            #pragma unroll
            for (int nt2 = 0; nt2 < 4; nt2++) {
                uint32_t bd = sb + 2*MM_TILE_B
                            + (wx * 64 + nt2 * 16 + brow) * MM_TSTRIDE_B + bcol;
                uint32_t r0, r1, r2, r3;
                ldmx4(r0, r1, r2, r3, bd);
                bF[nt2*2][0] = r0; bF[nt2*2][1] = r1;
                bF[nt2*2+1][0] = r2; bF[nt2*2+1][1] = r3;
            }
            #pragma unroll
            for (int mt = 0; mt < 2; mt++)
                #pragma unroll
                for (int nt = 0; nt < 8; nt++)
                    mma_fp16(acc[mt][nt], aF[mt], bF[nt]);    // A*Bl
        }
        __syncthreads();
    }

    // epilogue
    int r_base = row0 + wy * 32 + (lane >> 2);
    int c_base = col0 + wx * 64 + (lane & 3) * 2;
    #pragma unroll
    for (int mt = 0; mt < 2; mt++) {
        #pragma unroll
        for (int half = 0; half < 2; half++) {
            int r = r_base + mt * 16 + half * 8;
            #pragma unroll
            for (int nt = 0; nt < 8; nt++) {
                int cc = c_base + nt * 8;
                if (cc < N) {
                    float2 v = make_float2(acc[mt][nt][half*2], acc[mt][nt][half*2+1]);
                    if (EPI == 1) {
                        v.x += aux[cc]; v.y += aux[cc + 1];
                        v.x = (v.x > 20.f) ? v.x : log1pf(__expf(v.x));
                        v.y = (v.y > 20.f) ? v.y : log1pf(__expf(v.y));
                    } else if (EPI == 2) {
                        float2 a = *reinterpret_cast<const float2*>(
                            aux + (size_t)r * N + cc);
                        v.x += a.x; v.y += a.y;
                    }
                    *reinterpret_cast<float2*>(C + (size_t)r * N + cc) = v;
                }
            }
        }
    }
}

// ---------------- causal depthwise conv (K=4) + SiLU (fp32 + fp16) ----------------
__global__ void conv_silu_kernel(const float* __restrict__ xz,
                                 const float* __restrict__ conv_w,
                                 float* __restrict__ xact,
                                 __half* __restrict__ xah) {
    int e  = blockIdx.x * blockDim.x + threadIdx.x;
    int l0 = blockIdx.y * 64;
    int b  = blockIdx.z;
    float w0 = conv_w[e * 4 + 0];
    float w1 = conv_w[e * 4 + 1];
    float w2 = conv_w[e * 4 + 2];
    float w3 = conv_w[e * 4 + 3];
    float x0 = 0.f, x1 = 0.f, x2 = 0.f;
    #pragma unroll
    for (int j = -3; j < 0; j++) {
        int l = l0 + j;
        float v = (l >= 0) ? xz[((size_t)(b * SEQ + l)) * (2 * E_INNER) + e] : 0.f;
        x0 = x1; x1 = x2; x2 = v;
    }
    for (int i = 0; i < 64; i++) {
        int l = l0 + i;
        float x3 = xz[((size_t)(b * SEQ + l)) * (2 * E_INNER) + e];
        float s = w0 * x0 + w1 * x1 + w2 * x2 + w3 * x3;
        s = s / (1.f + __expf(-s));
        size_t idx = ((size_t)(b * SEQ + l)) * E_INNER + e;
        xact[idx] = s;
        xah[idx] = __float2half_rn(s);
        x0 = x1; x1 = x2; x2 = x3;
    }
}

// ---------------- selective scan + gate -> y (fp16) + h_last ----------------
__global__ void scan_kernel(const float* __restrict__ xz,
                            const float* __restrict__ xact,
                            const float* __restrict__ delta,
                            const float* __restrict__ xdb,
                            const float* __restrict__ A_log,
                            const float* __restrict__ D_param,
                            __half* __restrict__ yh,
                            float* __restrict__ hlast) {
    int gid = blockIdx.x * blockDim.x + threadIdx.x;
    int c = gid >> 4;
    int n = gid & 15;
    int b = c >> 11;
    int e = c & (E_INNER - 1);

    float An = -__expf(A_log[e * N_STATE + n]);
    float Dp = D_param[e];
    float h = 0.f;

    size_t tok = (size_t)b * SEQ;
    for (int l = 0; l < SEQ; l++) {
        size_t row = tok + l;
        float dlt = delta[row * E_INNER + e];
        float u   = xact [row * E_INNER + e];
        float Bv  = xdb[row * XDB_W + DT_RANK + n];
        float Cv  = xdb[row * XDB_W + DT_RANK + N_STATE + n];
        float dA  = __expf(dlt * An);
        h = fmaf(dA, h, dlt * u * Bv);
        float p = h * Cv;
        p += __shfl_xor_sync(0xffffffffu, p, 1, 16);
        p += __shfl_xor_sync(0xffffffffu, p, 2, 16);
        p += __shfl_xor_sync(0xffffffffu, p, 4, 16);
        p += __shfl_xor_sync(0xffffffffu, p, 8, 16);
        if (n == 0) {
            float zv = xz[row * (2 * E_INNER) + E_INNER + e];
            float yv = (p + u * Dp) * (zv / (1.f + __expf(-zv)));
            yh[row * E_INNER + e] = __float2half_rn(yv);
        }
    }
    hlast[(size_t)c * N_STATE + n] = h;
}

// ---------------- launch ----------------
extern "C" void kernel_launch(void* const* d_in, const int* in_sizes, int n_in,
                              void* d_out, int out_size) {
    const float* hidden  = (const float*)d_in[0];
    const float* norm_w  = (const float*)d_in[1];
    const float* W_in    = (const float*)d_in[2];
    const float* conv_w  = (const float*)d_in[3];
    const float* W_x     = (const float*)d_in[4];
    const float* W_dt    = (const float*)d_in[5];
    const float* b_dt    = (const float*)d_in[6];
    const float* A_log   = (const float*)d_in[7];
    const float* D_param = (const float*)d_in[8];
    const float* W_out   = (const float*)d_in[9];

    float* out   = (float*)d_out;
    float* hlast = out + (size_t)NTOK * D_MODEL;

    float *xz, *xact, *xdb, *delta;
    __half *xnh, *winh, *winl, *yh, *woth, *wotl;
    __half *xah, *wxh, *wxl, *wdth, *wdtl, *dth;
    cudaGetSymbolAddress((void**)&xz,    g_xz);
    cudaGetSymbolAddress((void**)&xact,  g_xact);
    cudaGetSymbolAddress((void**)&xdb,   g_xdb);
    cudaGetSymbolAddress((void**)&delta, g_delta);
    cudaGetSymbolAddress((void**)&xnh,   g_xnh);
    cudaGetSymbolAddress((void**)&winh,  g_winh);
    cudaGetSymbolAddress((void**)&winl,  g_winl);
    cudaGetSymbolAddress((void**)&yh,    g_yh);
    cudaGetSymbolAddress((void**)&woth,  g_woth);
    cudaGetSymbolAddress((void**)&wotl,  g_wotl);
    cudaGetSymbolAddress((void**)&xah,   g_xah);
    cudaGetSymbolAddress((void**)&wxh,   g_wxh);
    cudaGetSymbolAddress((void**)&wxl,   g_wxl);
    cudaGetSymbolAddress((void**)&wdth,  g_wdth);
    cudaGetSymbolAddress((void**)&wdtl,  g_wdtl);
    cudaGetSymbolAddress((void**)&dth,   g_dth);

    cudaFuncSetAttribute(gemm_mma_kernel,
                         cudaFuncAttributeMaxDynamicSharedMemorySize, MM_SMEM_B);

    // 1. RMSNorm -> fp16 (launch #1, so GEMM1 is launch #6 for ncu -s 5)
    rmsnorm_kernel<<<NTOK, 256>>>(hidden, norm_w, xnh);

    // 0. weight transposes + fp16 hi/lo splits (launches #2-#5)
    {
        dim3 b(32, 8);
        transpose_split_kernel<<<dim3(2*E_INNER/32, D_MODEL/32), b>>>(
            W_in, D_MODEL, 2*E_INNER, winh, winl);
        transpose_split_kernel<<<dim3(D_MODEL/32, E_INNER/32), b>>>(
            W_out, E_INNER, D_MODEL, woth, wotl);
        transpose_split_kernel<<<dim3((XDB_W + 31)/32, E_INNER/32), b>>>(
            W_x, E_INNER, XDB_W, wxh, wxl);
        transpose_split_kernel<<<dim3(E_INNER/32, DT_RANK/32), b>>>(
            W_dt, DT_RANK, E_INNER, wdth, wdtl);
    }

    // 2. GEMM1 (mma): xz = xnorm @ W_in   [4096,1024]x[1024,4096]
    gemm_mma_kernel<<<dim3(2*E_INNER/128, NTOK/128), 256, MM_SMEM_B>>>(
        xnh, winh, winl, xz, nullptr, 2*E_INNER, D_MODEL, 2*E_INNER, 0);

    // 3. causal dwconv + SiLU -> xact fp32 + fp16
    conv_silu_kernel<<<dim3(E_INNER/256, SEQ/64, BATCH), 256>>>(
        xz, conv_w, xact, xah);

    // 4. GEMM2 (mma): xdb = xact @ W_x   [4096,2048]x[2048,160]
    gemm_mma_kernel<<<dim3((XDB_W + 127)/128, NTOK/128), 256, MM_SMEM_B>>>(
        xah, wxh, wxl, xdb, nullptr, XDB_W, E_INNER, XDB_W, 0);

    // 5a. dt_lr -> fp16
    dt_split_kernel<<<NTOK, DT_RANK>>>(xdb, dth);

    // 5b. GEMM3 (mma): delta = softplus(dt_lr @ W_dt + b_dt)  [4096,64]x[64,2048]
    gemm_mma_kernel<<<dim3(E_INNER/128, NTOK/128), 256, MM_SMEM_B>>>(
        dth, wdth, wdtl, delta, b_dt, E_INNER, DT_RANK, E_INNER, 1);

    // 6. selective scan + gate -> y (fp16), h_last
    scan_kernel<<<(BATCH * E_INNER * N_STATE) / 256, 256>>>(
        xz, xact, delta, xdb, A_log, D_param, yh, hlast);

    // 7. GEMM4 (mma): out = residual + y @ W_out  [4096,2048]x[2048,1024]
    gemm_mma_kernel<<<dim3(D_MODEL/128, NTOK/128), 256, MM_SMEM_B>>>(
        yh, woth, wotl, out, hidden, D_MODEL, E_INNER, D_MODEL, 2);
}

// round 13
// speedup vs baseline: 2.7372x; 1.5911x over previous
#include <cuda_runtime.h>
#include <cuda_fp16.h>
#include <math.h>
#include <stdint.h>

#define D_MODEL 1024
#define N_STATE 16
#define E_INNER 2048
#define K_CONV  4
#define DT_RANK 64
#define BATCH   4
#define SEQ     1024
#define NTOK    (BATCH*SEQ)           // 4096
#define XDB_W   (DT_RANK + 2*N_STATE) // 160

// ---------------- scratch (device globals: allocation-free) ----------------
__device__ float g_xz   [(size_t)NTOK * 2 * E_INNER];    // 64 MB
__device__ float g_xact [(size_t)NTOK * E_INNER];        // 32 MB
__device__ float g_xdb  [(size_t)NTOK * XDB_W];          // 2.6 MB
__device__ float g_delta[(size_t)NTOK * E_INNER];        // 32 MB

__device__ __half g_xnh [(size_t)NTOK * D_MODEL];        // 8 MB
__device__ __half g_winh[(size_t)(2*E_INNER) * D_MODEL]; // 8 MB  (W_in^T hi)
__device__ __half g_winl[(size_t)(2*E_INNER) * D_MODEL]; // 8 MB  (W_in^T lo)
__device__ __half g_yh  [(size_t)NTOK * E_INNER];        // 16 MB
__device__ __half g_woth[(size_t)D_MODEL * E_INNER];     // 4 MB   (W_out^T hi)
__device__ __half g_wotl[(size_t)D_MODEL * E_INNER];     // 4 MB   (W_out^T lo)
__device__ __half g_xah [(size_t)NTOK * E_INNER];        // 16 MB
__device__ __half g_wxh [(size_t)XDB_W * E_INNER];       // 0.64 MB (W_x^T hi)
__device__ __half g_wxl [(size_t)XDB_W * E_INNER];       // 0.64 MB
__device__ __half g_wdth[(size_t)E_INNER * DT_RANK];     // 0.25 MB (W_dt^T hi)
__device__ __half g_wdtl[(size_t)E_INNER * DT_RANK];     // 0.25 MB
__device__ __half g_dth [(size_t)NTOK * DT_RANK];        // 0.5 MB

// ================= PTX helpers (baseline sm_80+ instructions only) =================
__device__ __forceinline__ uint32_t smem_u32(const void* p) {
    uint32_t a;
    asm("{ .reg .u64 t; cvta.to.shared.u64 t, %1; cvt.u32.u64 %0, t; }"
        : "=r"(a) : "l"(p));
    return a;
}
__device__ __forceinline__ void cp_async16(uint32_t dst, const void* src, int bytes) {
    asm volatile("cp.async.cg.shared.global [%0], [%1], 16, %2;"
                 :: "r"(dst), "l"(src), "r"(bytes) : "memory");
}
#define CP_COMMIT() asm volatile("cp.async.commit_group;" ::: "memory")
#define CP_WAIT(n)  asm volatile("cp.async.wait_group %0;" :: "n"(n) : "memory")

__device__ __forceinline__ void ldmx4(uint32_t& r0, uint32_t& r1,
                                      uint32_t& r2, uint32_t& r3, uint32_t addr) {
    asm volatile("ldmatrix.sync.aligned.m8n8.x4.shared.b16 {%0,%1,%2,%3}, [%4];"
                 : "=r"(r0), "=r"(r1), "=r"(r2), "=r"(r3) : "r"(addr));
}
__device__ __forceinline__ void mma_fp16(float* d, const uint32_t* a, const uint32_t* b) {
    asm volatile("mma.sync.aligned.m16n8k16.row.col.f32.f16.f16.f32 "
                 "{%0,%1,%2,%3}, {%4,%5,%6,%7}, {%8,%9}, {%0,%1,%2,%3};"
                 : "+f"(d[0]), "+f"(d[1]), "+f"(d[2]), "+f"(d[3])
                 : "r"(a[0]), "r"(a[1]), "r"(a[2]), "r"(a[3]),
                   "r"(b[0]), "r"(b[1]));
}

// swizzled smem offset within a 128-row x 128-byte tile (conflict-free SW128 pattern)
__device__ __forceinline__ uint32_t sw_off(int row, int chunk) {
    return (uint32_t)(row * 128 + ((chunk ^ (row & 7)) << 4));
}

// ---------------- RMSNorm -> fp16 (single rounding) ----------------
__global__ void rmsnorm_kernel(const float* __restrict__ x,
                               const float* __restrict__ w,
                               __half* __restrict__ oh) {
    int t   = blockIdx.x;
    int tid = threadIdx.x;         // 256 threads, 4 floats each
    const float4* xr = reinterpret_cast<const float4*>(x) + (size_t)t * (D_MODEL / 4);
    float4 xv = xr[tid];
    float s = xv.x*xv.x + xv.y*xv.y + xv.z*xv.z + xv.w*xv.w;
    #pragma unroll
    for (int o = 16; o > 0; o >>= 1) s += __shfl_xor_sync(0xffffffffu, s, o);
    __shared__ float red[8];
    if ((tid & 31) == 0) red[tid >> 5] = s;
    __syncthreads();
    if (tid == 0) {
        float tot = 0.f;
        #pragma unroll
        for (int i = 0; i < 8; i++) tot += red[i];
        red[0] = tot;
    }
    __syncthreads();
    float r = rsqrtf(red[0] * (1.0f / D_MODEL) + 1e-6f);
    float4 wv = reinterpret_cast<const float4*>(w)[tid];
    __half2* ohp = reinterpret_cast<__half2*>(oh) + (size_t)t * (D_MODEL / 2);
    ohp[tid*2+0] = __floats2half2_rn(xv.x * r * wv.x, xv.y * r * wv.y);
    ohp[tid*2+1] = __floats2half2_rn(xv.z * r * wv.z, xv.w * r * wv.w);
}

// ---------------- weight transpose + fp16 hi/lo split: W[K,N] -> T[N,K] ----------------
__global__ void transpose_split_kernel(const float* __restrict__ W, int K, int N,
                                       __half* __restrict__ Th,
                                       __half* __restrict__ Tl) {
    __shared__ float t[32][33];
    int n0 = blockIdx.x * 32, k0 = blockIdx.y * 32;
    int tx = threadIdx.x, ty = threadIdx.y;      // 32 x 8
    #pragma unroll
    for (int i = 0; i < 32; i += 8) {
        int kk = k0 + ty + i, nn = n0 + tx;
        t[ty + i][tx] = (kk < K && nn < N) ? W[(size_t)kk * N + nn] : 0.f;
    }
    __syncthreads();
    #pragma unroll
    for (int i = 0; i < 32; i += 8) {
        int nn = n0 + ty + i, kk = k0 + tx;
        if (nn < N && kk < K) {
            float v = t[tx][ty + i];
            __half h = __float2half_rn(v);
            float lo = v - __half2float(h);
            size_t o = (size_t)nn * K + kk;
            Th[o] = h;
            Tl[o] = __float2half_rn(lo);
        }
    }
}

// ---------------- dt_lr -> fp16: xdb[:, :64] ----------------
__global__ void dt_split_kernel(const float* __restrict__ xdb,
                                __half* __restrict__ dth) {
    int t = blockIdx.x;
    int c = threadIdx.x;     // 64
    dth[(size_t)t * DT_RANK + c] = __float2half_rn(xdb[(size_t)t * XDB_W + c]);
}

// ================ fp16 mma.sync GEMM (A single, B hi/lo: 2 MMAs) ================
// C[M,N] = A[M,K] @ B[N,K]^T; A single fp16, B split hi/lo fp16, K-major.
// CTA 128x128, BK=64 (128B swizzled rows, conflict-free), 8 warps (32x64 tile),
// 3-stage cp.async pipeline.
// EPI: 0 plain, 1 softplus(acc + aux[col]), 2 acc + aux[r*N+col] (residual)
#define MM_TILE_B    (128 * 128)           // 16384 bytes per operand tile
#define MM_STAGE_B   (3 * MM_TILE_B)       // 49152  (A, Bh, Bl)
#define MM_SMEM_B    (3 * MM_STAGE_B)      // 147456

__device__ __forceinline__ void mm_load_chunk(
    const __half* __restrict__ A,
    const __half* __restrict__ Bh, const __half* __restrict__ Bl,
    int K, int row0, int col0, int k0, int brows,
    uint32_t sbase, int tid) {
    #pragma unroll
    for (int i = 0; i < 4; i++) {
        int u = tid + i * 256;
        int r = u >> 3, c = u & 7;                 // row 0..127, 16B-chunk 0..7
        uint32_t sm = sbase + sw_off(r, c);
        cp_async16(sm, A + (size_t)(row0 + r) * K + k0 + c * 8, 16);
        int gbr = col0 + r;
        int bbytes = (gbr < brows) ? 16 : 0;
        int gbc = (gbr < brows) ? gbr : 0;
        size_t boff = (size_t)gbc * K + k0 + c * 8;
        cp_async16(sm + MM_TILE_B,     Bh + boff, bbytes);
        cp_async16(sm + 2*MM_TILE_B,   Bl + boff, bbytes);
    }
}

__global__ __launch_bounds__(256)
void gemm_mma_kernel(const __half* __restrict__ A,
                     const __half* __restrict__ Bh,
                     const __half* __restrict__ Bl,
                     float* __restrict__ C,
                     const float* __restrict__ aux,
                     int N, int K, int brows, int EPI) {
    extern __shared__ __align__(128) char sm[];
    uint32_t sm0 = smem_u32(sm);

    int tid = threadIdx.x;
    int wid = tid >> 5, lane = tid & 31;
    int wy = wid >> 1, wx = wid & 1;            // 4 x 2 warps
    int row0 = blockIdx.y * 128, col0 = blockIdx.x * 128;

    float acc[2][8][4];
    #pragma unroll
    for (int mt = 0; mt < 2; mt++)
        #pragma unroll
        for (int nt = 0; nt < 8; nt++)
            #pragma unroll
            for (int q = 0; q < 4; q++) acc[mt][nt][q] = 0.f;

    const int NC = K / 64;

    // prologue: 2 stages in flight
    mm_load_chunk(A, Bh, Bl, K, row0, col0, 0, brows, sm0, tid);
    CP_COMMIT();
    if (NC > 1) {
        mm_load_chunk(A, Bh, Bl, K, row0, col0, 64, brows, sm0 + MM_STAGE_B, tid);
        CP_COMMIT();
    }

    // frag row/chunk components
    int arow_l = lane & 15;          // row within 16-row block
    int achk_l = lane >> 4;          // 0/1 -> 16B chunk sub-index
    int brow_l = (lane & 7) + ((lane >> 4) << 3);
    int bchk_l = (lane >> 3) & 1;

    for (int c = 0; c < NC; c++) {
        if (c + 2 < NC) {
            mm_load_chunk(A, Bh, Bl, K, row0, col0, (c + 2) * 64, brows,
                          sm0 + ((c + 2) % 3) * MM_STAGE_B, tid);
            CP_COMMIT();
            CP_WAIT(2);
        } else if (c + 1 < NC) {
            CP_WAIT(1);
        } else {
            CP_WAIT(0);
        }
        __syncthreads();

        uint32_t sb = sm0 + (c % 3) * MM_STAGE_B;
        #pragma unroll
        for (int ks = 0; ks < 4; ks++) {           // 4 x K16 within BK=64
            uint32_t aF[2][4];
            int achk = ks * 2 + achk_l;
            #pragma unroll
            for (int mt = 0; mt < 2; mt++) {
                int ar = wy * 32 + mt * 16 + arow_l;
                uint32_t ad = sb + sw_off(ar, achk);
                ldmx4(aF[mt][0], aF[mt][1], aF[mt][2], aF[mt][3], ad);
            }
            uint32_t bF[8][2];
            int bchk = ks * 2 + bchk_l;
            #pragma unroll
            for (int nt2 = 0; nt2 < 4; nt2++) {
                int br = wx * 64 + nt2 * 16 + brow_l;
                uint32_t bd = sb + MM_TILE_B + sw_off(br, bchk);
                uint32_t r0, r1, r2, r3;
                ldmx4(r0, r1, r2, r3, bd);
                bF[nt2*2][0] = r0; bF[nt2*2][1] = r1;
                bF[nt2*2+1][0] = r2; bF[nt2*2+1][1] = r3;
            }
            #pragma unroll
            for (int mt = 0; mt < 2; mt++)
                #pragma unroll
                for (int nt = 0; nt < 8; nt++)
                    mma_fp16(acc[mt][nt], aF[mt], bF[nt]);    // A*Bh
            #pragma unroll
            for (int nt2 = 0; nt2 < 4; nt2++) {
                int br = wx * 64 + nt2 * 16 + brow_l;
                uint32_t bd = sb + 2*MM_TILE_B + sw_off(br, bchk);
                uint32_t r0, r1, r2, r3;
                ldmx4(r0, r1, r2, r3, bd);
                bF[nt2*2][0] = r0; bF[nt2*2][1] = r1;
                bF[nt2*2+1][0] = r2; bF[nt2*2+1][1] = r3;
            }
            #pragma unroll
            for (int mt = 0; mt < 2; mt++)
                #pragma unroll
                for (int nt = 0; nt < 8; nt++)
                    mma_fp16(acc[mt][nt], aF[mt], bF[nt]);    // A*Bl
        }
        __syncthreads();
    }

    // epilogue
    int r_base = row0 + wy * 32 + (lane >> 2);
    int c_base = col0 + wx * 64 + (lane & 3) * 2;
    #pragma unroll
    for (int mt = 0; mt < 2; mt++) {
        #pragma unroll
        for (int half = 0; half < 2; half++) {
            int r = r_base + mt * 16 + half * 8;
            #pragma unroll
            for (int nt = 0; nt < 8; nt++) {
                int cc = c_base + nt * 8;
                if (cc < N) {
                    float2 v = make_float2(acc[mt][nt][half*2], acc[mt][nt][half*2+1]);
                    if (EPI == 1) {
                        v.x += aux[cc]; v.y += aux[cc + 1];
                        v.x = (v.x > 20.f) ? v.x : __logf(1.f + __expf(v.x));
                        v.y = (v.y > 20.f) ? v.y : __logf(1.f + __expf(v.y));
                    } else if (EPI == 2) {
                        float2 a = *reinterpret_cast<const float2*>(
                            aux + (size_t)r * N + cc);
                        v.x += a.x; v.y += a.y;
                    }
                    *reinterpret_cast<float2*>(C + (size_t)r * N + cc) = v;
                }
            }
        }
    }
}

// ---------------- causal depthwise conv (K=4) + SiLU (fp32 + fp16) ----------------
__global__ void conv_silu_kernel(const float* __restrict__ xz,
                                 const float* __restrict__ conv_w,
                                 float* __restrict__ xact,
                                 __half* __restrict__ xah) {
    int e  = blockIdx.x * blockDim.x + threadIdx.x;
    int l0 = blockIdx.y * 64;
    int b  = blockIdx.z;
    float w0 = conv_w[e * 4 + 0];
    float w1 = conv_w[e * 4 + 1];
    float w2 = conv_w[e * 4 + 2];
    float w3 = conv_w[e * 4 + 3];
    float x0 = 0.f, x1 = 0.f, x2 = 0.f;
    #pragma unroll
    for (int j = -3; j < 0; j++) {
        int l = l0 + j;
        float v = (l >= 0) ? xz[((size_t)(b * SEQ + l)) * (2 * E_INNER) + e] : 0.f;
        x0 = x1; x1 = x2; x2 = v;
    }
    for (int i = 0; i < 64; i++) {
        int l = l0 + i;
        float x3 = xz[((size_t)(b * SEQ + l)) * (2 * E_INNER) + e];
        float s = w0 * x0 + w1 * x1 + w2 * x2 + w3 * x3;
        s = s / (1.f + __expf(-s));
        size_t idx = ((size_t)(b * SEQ + l)) * E_INNER + e;
        xact[idx] = s;
        xah[idx] = __float2half_rn(s);
        x0 = x1; x1 = x2; x2 = x3;
    }
}

// ---------------- selective scan + gate -> y (fp16) + h_last ----------------
// 16 lanes per (b,e) channel; loads software-pipelined ahead of the shfl chain.
__global__ void scan_kernel(const float* __restrict__ xz,
                            const float* __restrict__ xact,
                            const float* __restrict__ delta,
                            const float* __restrict__ xdb,
                            const float* __restrict__ A_log,
                            const float* __restrict__ D_param,
                            __half* __restrict__ yh,
                            float* __restrict__ hlast) {
    int gid = blockIdx.x * blockDim.x + threadIdx.x;
    int c = gid >> 4;
    int n = gid & 15;
    int b = c >> 11;
    int e = c & (E_INNER - 1);

    float An = -__expf(A_log[e * N_STATE + n]);
    float Dp = D_param[e];
    float h = 0.f;

    size_t tok = (size_t)b * SEQ;
    const float* dlt_p = delta + tok * E_INNER + e;
    const float* u_p   = xact  + tok * E_INNER + e;
    const float* bc_p  = xdb   + tok * XDB_W + DT_RANK + n;
    const float* z_p   = xz    + tok * (2 * E_INNER) + E_INNER + e;
    __half* y_p        = yh    + tok * E_INNER + e;

    // prime iteration 0
    float dlt = dlt_p[0];
    float u   = u_p[0];
    float Bv  = bc_p[0];
    float Cv  = bc_p[N_STATE];
    float zv  = z_p[0];

    for (int l = 0; l < SEQ; l++) {
        float dA = __expf(dlt * An);
        h = fmaf(dA, h, dlt * u * Bv);
        float p = h * Cv;
        float uD = u * Dp;
        float zc = zv;

        // prefetch next iteration BEFORE the shfl chain (hides L2 latency)
        if (l + 1 < SEQ) {
            size_t r1 = (size_t)(l + 1);
            dlt = dlt_p[r1 * E_INNER];
            u   = u_p  [r1 * E_INNER];
            Bv  = bc_p [r1 * XDB_W];
            Cv  = bc_p [r1 * XDB_W + N_STATE];
            zv  = z_p  [r1 * 2 * E_INNER];
        }

        p += __shfl_xor_sync(0xffffffffu, p, 1, 16);
        p += __shfl_xor_sync(0xffffffffu, p, 2, 16);
        p += __shfl_xor_sync(0xffffffffu, p, 4, 16);
        p += __shfl_xor_sync(0xffffffffu, p, 8, 16);
        if (n == 0) {
            float yv = (p + uD) * (zc / (1.f + __expf(-zc)));
            y_p[(size_t)l * E_INNER] = __float2half_rn(yv);
        }
    }
    hlast[(size_t)c * N_STATE + n] = h;
}

// ---------------- launch ----------------
extern "C" void kernel_launch(void* const* d_in, const int* in_sizes, int n_in,
                              void* d_out, int out_size) {
    const float* hidden  = (const float*)d_in[0];
    const float* norm_w  = (const float*)d_in[1];
    const float* W_in    = (const float*)d_in[2];
    const float* conv_w  = (const float*)d_in[3];
    const float* W_x     = (const float*)d_in[4];
    const float* W_dt    = (const float*)d_in[5];
    const float* b_dt    = (const float*)d_in[6];
    const float* A_log   = (const float*)d_in[7];
    const float* D_param = (const float*)d_in[8];
    const float* W_out   = (const float*)d_in[9];

    float* out   = (float*)d_out;
    float* hlast = out + (size_t)NTOK * D_MODEL;

    float *xz, *xact, *xdb, *delta;
    __half *xnh, *winh, *winl, *yh, *woth, *wotl;
    __half *xah, *wxh, *wxl, *wdth, *wdtl, *dth;
    cudaGetSymbolAddress((void**)&xz,    g_xz);
    cudaGetSymbolAddress((void**)&xact,  g_xact);
    cudaGetSymbolAddress((void**)&xdb,   g_xdb);
    cudaGetSymbolAddress((void**)&delta, g_delta);
    cudaGetSymbolAddress((void**)&xnh,   g_xnh);
    cudaGetSymbolAddress((void**)&winh,  g_winh);
    cudaGetSymbolAddress((void**)&winl,  g_winl);
    cudaGetSymbolAddress((void**)&yh,    g_yh);
    cudaGetSymbolAddress((void**)&woth,  g_woth);
    cudaGetSymbolAddress((void**)&wotl,  g_wotl);
    cudaGetSymbolAddress((void**)&xah,   g_xah);
    cudaGetSymbolAddress((void**)&wxh,   g_wxh);
    cudaGetSymbolAddress((void**)&wxl,   g_wxl);
    cudaGetSymbolAddress((void**)&wdth,  g_wdth);
    cudaGetSymbolAddress((void**)&wdtl,  g_wdtl);
    cudaGetSymbolAddress((void**)&dth,   g_dth);

    cudaFuncSetAttribute(gemm_mma_kernel,
                         cudaFuncAttributeMaxDynamicSharedMemorySize, MM_SMEM_B);

    // 1. RMSNorm -> fp16
    rmsnorm_kernel<<<NTOK, 256>>>(hidden, norm_w, xnh);

    // 0. weight transposes + fp16 hi/lo splits
    {
        dim3 b(32, 8);
        transpose_split_kernel<<<dim3(2*E_INNER/32, D_MODEL/32), b>>>(
            W_in, D_MODEL, 2*E_INNER, winh, winl);
        transpose_split_kernel<<<dim3(D_MODEL/32, E_INNER/32), b>>>(
            W_out, E_INNER, D_MODEL, woth, wotl);
        transpose_split_kernel<<<dim3((XDB_W + 31)/32, E_INNER/32), b>>>(
            W_x, E_INNER, XDB_W, wxh, wxl);
        transpose_split_kernel<<<dim3(E_INNER/32, DT_RANK/32), b>>>(
            W_dt, DT_RANK, E_INNER, wdth, wdtl);
    }

    // 2. GEMM1 (mma): xz = xnorm @ W_in   [4096,1024]x[1024,4096]
    gemm_mma_kernel<<<dim3(2*E_INNER/128, NTOK/128), 256, MM_SMEM_B>>>(
        xnh, winh, winl, xz, nullptr, 2*E_INNER, D_MODEL, 2*E_INNER, 0);

    // 3. causal dwconv + SiLU -> xact fp32 + fp16
    conv_silu_kernel<<<dim3(E_INNER/256, SEQ/64, BATCH), 256>>>(
        xz, conv_w, xact, xah);

    // 4. GEMM2 (mma): xdb = xact @ W_x   [4096,2048]x[2048,160]
    gemm_mma_kernel<<<dim3((XDB_W + 127)/128, NTOK/128), 256, MM_SMEM_B>>>(
        xah, wxh, wxl, xdb, nullptr, XDB_W, E_INNER, XDB_W, 0);

    // 5a. dt_lr -> fp16
    dt_split_kernel<<<NTOK, DT_RANK>>>(xdb, dth);

    // 5b. GEMM3 (mma): delta = softplus(dt_lr @ W_dt + b_dt)  [4096,64]x[64,2048]
    gemm_mma_kernel<<<dim3(E_INNER/128, NTOK/128), 256, MM_SMEM_B>>>(
        dth, wdth, wdtl, delta, b_dt, E_INNER, DT_RANK, E_INNER, 1);

    // 6. selective scan + gate -> y (fp16), h_last
    scan_kernel<<<(BATCH * E_INNER * N_STATE) / 256, 256>>>(
        xz, xact, delta, xdb, A_log, D_param, yh, hlast);

    // 7. GEMM4 (mma): out = residual + y @ W_out  [4096,2048]x[2048,1024]
    gemm_mma_kernel<<<dim3(D_MODEL/128, NTOK/128), 256, MM_SMEM_B>>>(
        yh, woth, wotl, out, hidden, D_MODEL, E_INNER, D_MODEL, 2);
}

// round 14
// speedup vs baseline: 3.0452x; 1.1125x over previous
#include <cuda_runtime.h>
#include <cuda_fp16.h>
#include <math.h>
#include <stdint.h>

#define D_MODEL 1024
#define N_STATE 16
#define E_INNER 2048
#define K_CONV  4
#define DT_RANK 64
#define BATCH   4
#define SEQ     1024
#define NTOK    (BATCH*SEQ)           // 4096
#define XDB_W   (DT_RANK + 2*N_STATE) // 160

// ---------------- scratch (device globals: allocation-free) ----------------
__device__ float g_xz   [(size_t)NTOK * 2 * E_INNER];    // 64 MB
__device__ float g_xact [(size_t)NTOK * E_INNER];        // 32 MB
__device__ float g_xdb  [(size_t)NTOK * XDB_W];          // 2.6 MB
__device__ float g_delta[(size_t)NTOK * E_INNER];        // 32 MB

__device__ __half g_xnh [(size_t)NTOK * D_MODEL];        // 8 MB
__device__ __half g_winh[(size_t)(2*E_INNER) * D_MODEL]; // 8 MB  (W_in^T hi)
__device__ __half g_yh  [(size_t)NTOK * E_INNER];        // 16 MB
__device__ __half g_woth[(size_t)D_MODEL * E_INNER];     // 4 MB   (W_out^T hi)
__device__ __half g_xah [(size_t)NTOK * E_INNER];        // 16 MB
__device__ __half g_wxh [(size_t)XDB_W * E_INNER];       // 0.64 MB (W_x^T hi)
__device__ __half g_wxl [(size_t)XDB_W * E_INNER];       // 0.64 MB
__device__ __half g_wdth[(size_t)E_INNER * DT_RANK];     // 0.25 MB (W_dt^T hi)
__device__ __half g_wdtl[(size_t)E_INNER * DT_RANK];     // 0.25 MB
__device__ __half g_dth [(size_t)NTOK * DT_RANK];        // 0.5 MB

// ================= PTX helpers (baseline sm_80+ instructions only) =================
__device__ __forceinline__ uint32_t smem_u32(const void* p) {
    uint32_t a;
    asm("{ .reg .u64 t; cvta.to.shared.u64 t, %1; cvt.u32.u64 %0, t; }"
        : "=r"(a) : "l"(p));
    return a;
}
__device__ __forceinline__ void cp_async16(uint32_t dst, const void* src, int bytes) {
    asm volatile("cp.async.cg.shared.global [%0], [%1], 16, %2;"
                 :: "r"(dst), "l"(src), "r"(bytes) : "memory");
}
#define CP_COMMIT() asm volatile("cp.async.commit_group;" ::: "memory")
#define CP_WAIT(n)  asm volatile("cp.async.wait_group %0;" :: "n"(n) : "memory")

__device__ __forceinline__ void ldmx4(uint32_t& r0, uint32_t& r1,
                                      uint32_t& r2, uint32_t& r3, uint32_t addr) {
    asm volatile("ldmatrix.sync.aligned.m8n8.x4.shared.b16 {%0,%1,%2,%3}, [%4];"
                 : "=r"(r0), "=r"(r1), "=r"(r2), "=r"(r3) : "r"(addr));
}
__device__ __forceinline__ void mma_fp16(float* d, const uint32_t* a, const uint32_t* b) {
    asm volatile("mma.sync.aligned.m16n8k16.row.col.f32.f16.f16.f32 "
                 "{%0,%1,%2,%3}, {%4,%5,%6,%7}, {%8,%9}, {%0,%1,%2,%3};"
                 : "+f"(d[0]), "+f"(d[1]), "+f"(d[2]), "+f"(d[3])
                 : "r"(a[0]), "r"(a[1]), "r"(a[2]), "r"(a[3]),
                   "r"(b[0]), "r"(b[1]));
}

// swizzled smem offset within a 128-row x 128-byte tile (conflict-free SW128 pattern)
__device__ __forceinline__ uint32_t sw_off(int row, int chunk) {
    return (uint32_t)(row * 128 + ((chunk ^ (row & 7)) << 4));
}

// ---------------- RMSNorm -> fp16 (single rounding) ----------------
__global__ void rmsnorm_kernel(const float* __restrict__ x,
                               const float* __restrict__ w,
                               __half* __restrict__ oh) {
    int t   = blockIdx.x;
    int tid = threadIdx.x;         // 256 threads, 4 floats each
    const float4* xr = reinterpret_cast<const float4*>(x) + (size_t)t * (D_MODEL / 4);
    float4 xv = xr[tid];
    float s = xv.x*xv.x + xv.y*xv.y + xv.z*xv.z + xv.w*xv.w;
    #pragma unroll
    for (int o = 16; o > 0; o >>= 1) s += __shfl_xor_sync(0xffffffffu, s, o);
    __shared__ float red[8];
    if ((tid & 31) == 0) red[tid >> 5] = s;
    __syncthreads();
    if (tid == 0) {
        float tot = 0.f;
        #pragma unroll
        for (int i = 0; i < 8; i++) tot += red[i];
        red[0] = tot;
    }
    __syncthreads();
    float r = rsqrtf(red[0] * (1.0f / D_MODEL) + 1e-6f);
    float4 wv = reinterpret_cast<const float4*>(w)[tid];
    __half2* ohp = reinterpret_cast<__half2*>(oh) + (size_t)t * (D_MODEL / 2);
    ohp[tid*2+0] = __floats2half2_rn(xv.x * r * wv.x, xv.y * r * wv.y);
    ohp[tid*2+1] = __floats2half2_rn(xv.z * r * wv.z, xv.w * r * wv.w);
}

// ---------------- weight transpose + fp16 split: W[K,N] -> T[N,K] (Tl optional) ----------------
__global__ void transpose_split_kernel(const float* __restrict__ W, int K, int N,
                                       __half* __restrict__ Th,
                                       __half* __restrict__ Tl) {
    __shared__ float t[32][33];
    int n0 = blockIdx.x * 32, k0 = blockIdx.y * 32;
    int tx = threadIdx.x, ty = threadIdx.y;      // 32 x 8
    #pragma unroll
    for (int i = 0; i < 32; i += 8) {
        int kk = k0 + ty + i, nn = n0 + tx;
        t[ty + i][tx] = (kk < K && nn < N) ? W[(size_t)kk * N + nn] : 0.f;
    }
    __syncthreads();
    #pragma unroll
    for (int i = 0; i < 32; i += 8) {
        int nn = n0 + ty + i, kk = k0 + tx;
        if (nn < N && kk < K) {
            float v = t[tx][ty + i];
            __half h = __float2half_rn(v);
            size_t o = (size_t)nn * K + kk;
            Th[o] = h;
            if (Tl) Tl[o] = __float2half_rn(v - __half2float(h));
        }
    }
}

// ---------------- dt_lr -> fp16: xdb[:, :64] ----------------
__global__ void dt_split_kernel(const float* __restrict__ xdb,
                                __half* __restrict__ dth) {
    int t = blockIdx.x;
    int c = threadIdx.x;     // 64
    dth[(size_t)t * DT_RANK + c] = __float2half_rn(xdb[(size_t)t * XDB_W + c]);
}

// ================ fp16 mma.sync GEMM ================
// C[M,N] = A[M,K] @ B[N,K]^T; A single fp16; B hi (+ optional lo for 2-term).
// CTA 128x128, BK=64 (128B swizzled rows, conflict-free), 8 warps (32x64 tile),
// 3-stage cp.async pipeline.
// EPI: 0 plain, 1 softplus(acc + aux[col]), 2 acc + aux[r*N+col] (residual)
#define MM_TILE_B    (128 * 128)           // 16384 bytes per operand tile
#define MM_STAGE_B   (3 * MM_TILE_B)       // 49152  (A, Bh, Bl)
#define MM_SMEM_B    (3 * MM_STAGE_B)      // 147456

__device__ __forceinline__ void mm_load_chunk(
    const __half* __restrict__ A,
    const __half* __restrict__ Bh, const __half* __restrict__ Bl,
    int K, int row0, int col0, int k0, int brows,
    uint32_t sbase, int tid) {
    #pragma unroll
    for (int i = 0; i < 4; i++) {
        int u = tid + i * 256;
        int r = u >> 3, c = u & 7;                 // row 0..127, 16B-chunk 0..7
        uint32_t sm = sbase + sw_off(r, c);
        cp_async16(sm, A + (size_t)(row0 + r) * K + k0 + c * 8, 16);
        int gbr = col0 + r;
        int bbytes = (gbr < brows) ? 16 : 0;
        int gbc = (gbr < brows) ? gbr : 0;
        size_t boff = (size_t)gbc * K + k0 + c * 8;
        cp_async16(sm + MM_TILE_B, Bh + boff, bbytes);
        if (Bl) cp_async16(sm + 2*MM_TILE_B, Bl + boff, bbytes);
    }
}

__global__ __launch_bounds__(256)
void gemm_mma_kernel(const __half* __restrict__ A,
                     const __half* __restrict__ Bh,
                     const __half* __restrict__ Bl,
                     float* __restrict__ C,
                     const float* __restrict__ aux,
                     int N, int K, int brows, int EPI) {
    extern __shared__ __align__(128) char sm[];
    uint32_t sm0 = smem_u32(sm);

    int tid = threadIdx.x;
    int wid = tid >> 5, lane = tid & 31;
    int wy = wid >> 1, wx = wid & 1;            // 4 x 2 warps
    int row0 = blockIdx.y * 128, col0 = blockIdx.x * 128;

    float acc[2][8][4];
    #pragma unroll
    for (int mt = 0; mt < 2; mt++)
        #pragma unroll
        for (int nt = 0; nt < 8; nt++)
            #pragma unroll
            for (int q = 0; q < 4; q++) acc[mt][nt][q] = 0.f;

    const int NC = K / 64;

    // prologue: 2 stages in flight
    mm_load_chunk(A, Bh, Bl, K, row0, col0, 0, brows, sm0, tid);
    CP_COMMIT();
    if (NC > 1) {
        mm_load_chunk(A, Bh, Bl, K, row0, col0, 64, brows, sm0 + MM_STAGE_B, tid);
        CP_COMMIT();
    }

    // frag row/chunk components
    int arow_l = lane & 15;          // row within 16-row block
    int achk_l = lane >> 4;          // 0/1 -> 16B chunk sub-index
    int brow_l = (lane & 7) + ((lane >> 4) << 3);
    int bchk_l = (lane >> 3) & 1;

    for (int c = 0; c < NC; c++) {
        if (c + 2 < NC) {
            mm_load_chunk(A, Bh, Bl, K, row0, col0, (c + 2) * 64, brows,
                          sm0 + ((c + 2) % 3) * MM_STAGE_B, tid);
            CP_COMMIT();
            CP_WAIT(2);
        } else if (c + 1 < NC) {
            CP_WAIT(1);
        } else {
            CP_WAIT(0);
        }
        __syncthreads();

        uint32_t sb = sm0 + (c % 3) * MM_STAGE_B;
        #pragma unroll
        for (int ks = 0; ks < 4; ks++) {           // 4 x K16 within BK=64
            uint32_t aF[2][4];
            int achk = ks * 2 + achk_l;
            #pragma unroll
            for (int mt = 0; mt < 2; mt++) {
                int ar = wy * 32 + mt * 16 + arow_l;
                uint32_t ad = sb + sw_off(ar, achk);
                ldmx4(aF[mt][0], aF[mt][1], aF[mt][2], aF[mt][3], ad);
            }
            uint32_t bF[8][2];
            int bchk = ks * 2 + bchk_l;
            #pragma unroll
            for (int nt2 = 0; nt2 < 4; nt2++) {
                int br = wx * 64 + nt2 * 16 + brow_l;
                uint32_t bd = sb + MM_TILE_B + sw_off(br, bchk);
                uint32_t r0, r1, r2, r3;
                ldmx4(r0, r1, r2, r3, bd);
                bF[nt2*2][0] = r0; bF[nt2*2][1] = r1;
                bF[nt2*2+1][0] = r2; bF[nt2*2+1][1] = r3;
            }
            #pragma unroll
            for (int mt = 0; mt < 2; mt++)
                #pragma unroll
                for (int nt = 0; nt < 8; nt++)
                    mma_fp16(acc[mt][nt], aF[mt], bF[nt]);    // A*Bh
            if (Bl) {
                #pragma unroll
                for (int nt2 = 0; nt2 < 4; nt2++) {
                    int br = wx * 64 + nt2 * 16 + brow_l;
                    uint32_t bd = sb + 2*MM_TILE_B + sw_off(br, bchk);
                    uint32_t r0, r1, r2, r3;
                    ldmx4(r0, r1, r2, r3, bd);
                    bF[nt2*2][0] = r0; bF[nt2*2][1] = r1;
                    bF[nt2*2+1][0] = r2; bF[nt2*2+1][1] = r3;
                }
                #pragma unroll
                for (int mt = 0; mt < 2; mt++)
                    #pragma unroll
                    for (int nt = 0; nt < 8; nt++)
                        mma_fp16(acc[mt][nt], aF[mt], bF[nt]);    // A*Bl
            }
        }
        __syncthreads();
    }

    // epilogue
    int r_base = row0 + wy * 32 + (lane >> 2);
    int c_base = col0 + wx * 64 + (lane & 3) * 2;
    #pragma unroll
    for (int mt = 0; mt < 2; mt++) {
        #pragma unroll
        for (int half = 0; half < 2; half++) {
            int r = r_base + mt * 16 + half * 8;
            #pragma unroll
            for (int nt = 0; nt < 8; nt++) {
                int cc = c_base + nt * 8;
                if (cc < N) {
                    float2 v = make_float2(acc[mt][nt][half*2], acc[mt][nt][half*2+1]);
                    if (EPI == 1) {
                        v.x += aux[cc]; v.y += aux[cc + 1];
                        v.x = (v.x > 20.f) ? v.x : __logf(1.f + __expf(v.x));
                        v.y = (v.y > 20.f) ? v.y : __logf(1.f + __expf(v.y));
                    } else if (EPI == 2) {
                        float2 a = *reinterpret_cast<const float2*>(
                            aux + (size_t)r * N + cc);
                        v.x += a.x; v.y += a.y;
                    }
                    *reinterpret_cast<float2*>(C + (size_t)r * N + cc) = v;
                }
            }
        }
    }
}

// ---------------- causal depthwise conv (K=4) + SiLU (fp32 + fp16) ----------------
__global__ void conv_silu_kernel(const float* __restrict__ xz,
                                 const float* __restrict__ conv_w,
                                 float* __restrict__ xact,
                                 __half* __restrict__ xah) {
    int e  = blockIdx.x * blockDim.x + threadIdx.x;
    int l0 = blockIdx.y * 64;
    int b  = blockIdx.z;
    float w0 = conv_w[e * 4 + 0];
    float w1 = conv_w[e * 4 + 1];
    float w2 = conv_w[e * 4 + 2];
    float w3 = conv_w[e * 4 + 3];
    float x0 = 0.f, x1 = 0.f, x2 = 0.f;
    #pragma unroll
    for (int j = -3; j < 0; j++) {
        int l = l0 + j;
        float v = (l >= 0) ? xz[((size_t)(b * SEQ + l)) * (2 * E_INNER) + e] : 0.f;
        x0 = x1; x1 = x2; x2 = v;
    }
    for (int i = 0; i < 64; i++) {
        int l = l0 + i;
        float x3 = xz[((size_t)(b * SEQ + l)) * (2 * E_INNER) + e];
        float s = w0 * x0 + w1 * x1 + w2 * x2 + w3 * x3;
        s = s / (1.f + __expf(-s));
        size_t idx = ((size_t)(b * SEQ + l)) * E_INNER + e;
        xact[idx] = s;
        xah[idx] = __float2half_rn(s);
        x0 = x1; x1 = x2; x2 = x3;
    }
}

// ---------------- selective scan + gate -> y (fp16) + h_last ----------------
// 16 lanes per (b,e) channel; loads software-pipelined ahead of the shfl chain.
__global__ void scan_kernel(const float* __restrict__ xz,
                            const float* __restrict__ xact,
                            const float* __restrict__ delta,
                            const float* __restrict__ xdb,
                            const float* __restrict__ A_log,
                            const float* __restrict__ D_param,
                            __half* __restrict__ yh,
                            float* __restrict__ hlast) {
    int gid = blockIdx.x * blockDim.x + threadIdx.x;
    int c = gid >> 4;
    int n = gid & 15;
    int b = c >> 11;
    int e = c & (E_INNER - 1);

    float An = -__expf(A_log[e * N_STATE + n]);
    float Dp = D_param[e];
    float h = 0.f;

    size_t tok = (size_t)b * SEQ;
    const float* dlt_p = delta + tok * E_INNER + e;
    const float* u_p   = xact  + tok * E_INNER + e;
    const float* bc_p  = xdb   + tok * XDB_W + DT_RANK + n;
    const float* z_p   = xz    + tok * (2 * E_INNER) + E_INNER + e;
    __half* y_p        = yh    + tok * E_INNER + e;

    // prime iteration 0
    float dlt = dlt_p[0];
    float u   = u_p[0];
    float Bv  = bc_p[0];
    float Cv  = bc_p[N_STATE];
    float zv  = z_p[0];

    for (int l = 0; l < SEQ; l++) {
        float dA = __expf(dlt * An);
        h = fmaf(dA, h, dlt * u * Bv);
        float p = h * Cv;
        float uD = u * Dp;
        float zc = zv;

        // prefetch next iteration BEFORE the shfl chain (hides L2 latency)
        if (l + 1 < SEQ) {
            size_t r1 = (size_t)(l + 1);
            dlt = dlt_p[r1 * E_INNER];
            u   = u_p  [r1 * E_INNER];
            Bv  = bc_p [r1 * XDB_W];
            Cv  = bc_p [r1 * XDB_W + N_STATE];
            zv  = z_p  [r1 * 2 * E_INNER];
        }

        p += __shfl_xor_sync(0xffffffffu, p, 1, 16);
        p += __shfl_xor_sync(0xffffffffu, p, 2, 16);
        p += __shfl_xor_sync(0xffffffffu, p, 4, 16);
        p += __shfl_xor_sync(0xffffffffu, p, 8, 16);
        if (n == 0) {
            float yv = (p + uD) * (zc / (1.f + __expf(-zc)));
            y_p[(size_t)l * E_INNER] = __float2half_rn(yv);
        }
    }
    hlast[(size_t)c * N_STATE + n] = h;
}

// ---------------- launch ----------------
extern "C" void kernel_launch(void* const* d_in, const int* in_sizes, int n_in,
                              void* d_out, int out_size) {
    const float* hidden  = (const float*)d_in[0];
    const float* norm_w  = (const float*)d_in[1];
    const float* W_in    = (const float*)d_in[2];
    const float* conv_w  = (const float*)d_in[3];
    const float* W_x     = (const float*)d_in[4];
    const float* W_dt    = (const float*)d_in[5];
    const float* b_dt    = (const float*)d_in[6];
    const float* A_log   = (const float*)d_in[7];
    const float* D_param = (const float*)d_in[8];
    const float* W_out   = (const float*)d_in[9];

    float* out   = (float*)d_out;
    float* hlast = out + (size_t)NTOK * D_MODEL;

    float *xz, *xact, *xdb, *delta;
    __half *xnh, *winh, *yh, *woth;
    __half *xah, *wxh, *wxl, *wdth, *wdtl, *dth;
    cudaGetSymbolAddress((void**)&xz,    g_xz);
    cudaGetSymbolAddress((void**)&xact,  g_xact);
    cudaGetSymbolAddress((void**)&xdb,   g_xdb);
    cudaGetSymbolAddress((void**)&delta, g_delta);
    cudaGetSymbolAddress((void**)&xnh,   g_xnh);
    cudaGetSymbolAddress((void**)&winh,  g_winh);
    cudaGetSymbolAddress((void**)&yh,    g_yh);
    cudaGetSymbolAddress((void**)&woth,  g_woth);
    cudaGetSymbolAddress((void**)&xah,   g_xah);
    cudaGetSymbolAddress((void**)&wxh,   g_wxh);
    cudaGetSymbolAddress((void**)&wxl,   g_wxl);
    cudaGetSymbolAddress((void**)&wdth,  g_wdth);
    cudaGetSymbolAddress((void**)&wdtl,  g_wdtl);
    cudaGetSymbolAddress((void**)&dth,   g_dth);

    cudaFuncSetAttribute(gemm_mma_kernel,
                         cudaFuncAttributeMaxDynamicSharedMemorySize, MM_SMEM_B);

    // 1. RMSNorm -> fp16
    rmsnorm_kernel<<<NTOK, 256>>>(hidden, norm_w, xnh);

    // 0. weight transposes (single-term for W_in/W_out; 2-term for W_x/W_dt)
    {
        dim3 b(32, 8);
        transpose_split_kernel<<<dim3(2*E_INNER/32, D_MODEL/32), b>>>(
            W_in, D_MODEL, 2*E_INNER, winh, nullptr);
        transpose_split_kernel<<<dim3(D_MODEL/32, E_INNER/32), b>>>(
            W_out, E_INNER, D_MODEL, woth, nullptr);
        transpose_split_kernel<<<dim3((XDB_W + 31)/32, E_INNER/32), b>>>(
            W_x, E_INNER, XDB_W, wxh, wxl);
        transpose_split_kernel<<<dim3(E_INNER/32, DT_RANK/32), b>>>(
            W_dt, DT_RANK, E_INNER, wdth, wdtl);
    }

    // 2. GEMM1 (mma, single-term): xz = xnorm @ W_in   [4096,1024]x[1024,4096]
    gemm_mma_kernel<<<dim3(2*E_INNER/128, NTOK/128), 256, MM_SMEM_B>>>(
        xnh, winh, nullptr, xz, nullptr, 2*E_INNER, D_MODEL, 2*E_INNER, 0);

    // 3. causal dwconv + SiLU -> xact fp32 + fp16
    conv_silu_kernel<<<dim3(E_INNER/256, SEQ/64, BATCH), 256>>>(
        xz, conv_w, xact, xah);

    // 4. GEMM2 (mma, 2-term): xdb = xact @ W_x   [4096,2048]x[2048,160]
    gemm_mma_kernel<<<dim3((XDB_W + 127)/128, NTOK/128), 256, MM_SMEM_B>>>(
        xah, wxh, wxl, xdb, nullptr, XDB_W, E_INNER, XDB_W, 0);

    // 5a. dt_lr -> fp16
    dt_split_kernel<<<NTOK, DT_RANK>>>(xdb, dth);

    // 5b. GEMM3 (mma, 2-term): delta = softplus(dt_lr @ W_dt + b_dt)
    gemm_mma_kernel<<<dim3(E_INNER/128, NTOK/128), 256, MM_SMEM_B>>>(
        dth, wdth, wdtl, delta, b_dt, E_INNER, DT_RANK, E_INNER, 1);

    // 6. selective scan + gate -> y (fp16), h_last
    scan_kernel<<<(BATCH * E_INNER * N_STATE) / 256, 256>>>(
        xz, xact, delta, xdb, A_log, D_param, yh, hlast);

    // 7. GEMM4 (mma, single-term): out = residual + y @ W_out  [4096,2048]x[2048,1024]
    gemm_mma_kernel<<<dim3(D_MODEL/128, NTOK/128), 256, MM_SMEM_B>>>(
        yh, woth, nullptr, out, hidden, D_MODEL, E_INNER, D_MODEL, 2);
}